// round 15
// baseline (speedup 1.0000x reference)
#include <cuda_runtime.h>
#include <cuda_bf16.h>
#include <math.h>
#include <stdint.h>

#define BB     2
#define CEMB   256
#define KLAT   128
#define NLON   256
#define MM     129
#define MMP    136
#define LL     128
#define HID    512
#define NLAYER 4
#define PIX    (KLAT*NLON)
#define BC     (BB*CEMB)
#define ROWS2  (BB*MM)
#define RC     (ROWS2*CEMB)
#define BCK    (BC*KLAT)
#define NP     320
#define KINV   272

typedef unsigned long long ull;
typedef unsigned short ushort_t;

// ---------------- scratch ----------------
__device__ float g_h [BB*CEMB*PIX];
__device__ float g_t [BB*HID*PIX];
__device__ float g_Fr[MM*BCK];
__device__ float g_Fi[MM*BCK];
__device__ float g_Dr[LL*RC];
__device__ float g_Di[LL*RC];
__device__ float g_Er[LL*RC];
__device__ float g_Ei[LL*RC];
__device__ float g_Yr[(size_t)MMP*BCK];
__device__ float g_Yi[(size_t)MMP*BCK];
// spec_w bf16 hi/lo planes  [layer][l][i][o]
__device__ ushort_t g_Brh[(size_t)NLAYER*LL*CEMB*CEMB];
__device__ ushort_t g_Brl[(size_t)NLAYER*LL*CEMB*CEMB];
__device__ ushort_t g_Bih[(size_t)NLAYER*LL*CEMB*CEMB];
__device__ ushort_t g_Bil[(size_t)NLAYER*LL*CEMB*CEMB];
// static bf16 hi/lo planes
__device__ ushort_t g_dfh[NLON*NP], g_dfl[NLON*NP];
__device__ ushort_t g_dih[KINV*NLON], g_dil[KINV*NLON];
__device__ ushort_t g_wth[MM*LL*KLAT], g_wtl[MM*LL*KLAT];
__device__ ushort_t g_iwh[MM*LL*KLAT], g_iwl[MM*LL*KLAT];

__device__ __forceinline__ float gelu_tanh(float x){
    float x3 = x*x*x;
    float z = 0.7978845608028654f*fmaf(0.044715f, x3, x);
    float t;
    asm("tanh.approx.f32 %0, %1;" : "=f"(t) : "f"(z));
    return 0.5f*x*(1.f + t);
}
__device__ __forceinline__ void bfsplit(float v, unsigned short &h, unsigned short &l){
    __nv_bfloat16 hb = __float2bfloat16(v);
    float r = v - __bfloat162float(hb);
    h = __bfloat16_as_ushort(hb);
    l = __bfloat16_as_ushort(__float2bfloat16(r));
}
__device__ __forceinline__ float bf2f(unsigned short u){
    return __bfloat162float(__ushort_as_bfloat16(u));
}
__device__ __forceinline__ uint32_t smem_u32(const void* p){
    uint32_t a;
    asm("{ .reg .u64 t; cvta.to.shared.u64 t, %1; cvt.u32.u64 %0, t; }" : "=r"(a) : "l"(p));
    return a;
}
#define LDSM4(r0,r1,r2,r3,addr) \
    asm volatile("ldmatrix.sync.aligned.m8n8.x4.shared.b16 {%0,%1,%2,%3}, [%4];" \
        : "=r"(r0),"=r"(r1),"=r"(r2),"=r"(r3) : "r"(addr))
#define LDSM4T(r0,r1,r2,r3,addr) \
    asm volatile("ldmatrix.sync.aligned.m8n8.x4.trans.shared.b16 {%0,%1,%2,%3}, [%4];" \
        : "=r"(r0),"=r"(r1),"=r"(r2),"=r"(r3) : "r"(addr))
#define MMA_BF16(d, a, b0, b1) \
    asm volatile("mma.sync.aligned.m16n8k16.row.col.f32.bf16.bf16.f32 " \
        "{%0,%1,%2,%3}, {%4,%5,%6,%7}, {%8,%9}, {%0,%1,%2,%3};" \
        : "+f"(d[0]),"+f"(d[1]),"+f"(d[2]),"+f"(d[3]) \
        : "r"(a[0]),"r"(a[1]),"r"(a[2]),"r"(a[3]), "r"(b0),"r"(b1))

// ---------------- init ----------------
__global__ void k_dftinit(){
    int c = blockIdx.x;
    int n = threadIdx.x;
    float fwdv = 0.f, invv = 0.f;
    if (c < 2*MM){
        int m = c >> 1;
        int ph = (m*n) & 255;
        double a = 6.283185307179586476925286766559 * (double)ph / 256.0;
        double base = (c & 1) ? -sin(a) : cos(a);
        fwdv = (float)(base * (6.283185307179586476925286766559/256.0));
        double s = (m==0 || m==MM-1) ? 1.0 : 2.0;
        invv = (float)(base * s);
    }
    unsigned short fh, fl;
    bfsplit(fwdv, fh, fl);
    g_dfh[(size_t)n*NP + c] = fh;
    g_dfl[(size_t)n*NP + c] = fl;
    if (c < KINV){
        unsigned short ih, il;
        bfsplit(invv, ih, il);
        g_dih[(size_t)c*NLON + n] = ih;
        g_dil[(size_t)c*NLON + n] = il;
    }
}

__global__ void k_wsplit(const float* __restrict__ wt, ushort_t* __restrict__ h,
                         ushort_t* __restrict__ l){
    size_t i = (size_t)blockIdx.x*128 + threadIdx.x;
    float v = wt[i];
    unsigned short hh, ll;
    bfsplit(v, hh, ll);
    h[i] = hh;
    l[i] = ll;
}

// spec_w [L][i][o][l][2] -> bf16 planes [layer][l][i][o]; packed uint32 stores
__global__ void k_wtrans(const float* __restrict__ sw){
    __shared__ float2 tile[32][33];
    const int lt = blockIdx.x & 3;
    const int ot = blockIdx.x >> 2;
    const int i  = blockIdx.y;
    const int ly = blockIdx.z;
    const int l0 = lt*32, o0 = ot*32;
    const int x = threadIdx.x, y = threadIdx.y;
    for (int r=y; r<32; r+=8){
        size_t src = (((size_t)(ly*CEMB + i))*CEMB + (o0+r))*LL + l0 + x;
        tile[r][x] = *(const float2*)(sw + src*2);
    }
    __syncthreads();
    const int xx = x & 15, xh = x >> 4;
    #pragma unroll
    for (int j=0;j<2;j++){
        int r = y*2 + xh + 16*j;
        float2 wa = tile[2*xx][r];
        float2 wb = tile[2*xx+1][r];
        unsigned short rha,rla,iha,ila, rhb,rlb,ihb,ilb;
        bfsplit(wa.x, rha, rla); bfsplit(wa.y, iha, ila);
        bfsplit(wb.x, rhb, rlb); bfsplit(wb.y, ihb, ilb);
        size_t dst = (((size_t)(ly*LL + l0 + r))*CEMB + i)*CEMB + o0 + 2*xx;
        *(uint32_t*)&g_Brh[dst] = (uint32_t)rha | ((uint32_t)rhb<<16);
        *(uint32_t*)&g_Brl[dst] = (uint32_t)rla | ((uint32_t)rlb<<16);
        *(uint32_t*)&g_Bih[dst] = (uint32_t)iha | ((uint32_t)ihb<<16);
        *(uint32_t*)&g_Bil[dst] = (uint32_t)ila | ((uint32_t)ilb<<16);
    }
}

// encoder: o-dim split over blockIdx.z
__global__ void k_encoder(const float* __restrict__ x, const float* __restrict__ wenc,
                          const float* __restrict__ benc, const float* __restrict__ pos){
    int b  = blockIdx.y;
    int p0 = blockIdx.x*256;
    int oc = blockIdx.z*64;
    int t  = threadIdx.x;
    __shared__ float ws[64][8];
    if (t < 64){
        #pragma unroll
        for (int j=0;j<8;j++) ws[t][j] = wenc[(oc+t)*8+j];
    }
    __syncthreads();
    float xv[8];
    #pragma unroll
    for (int c=0;c<8;c++) xv[c] = x[((size_t)b*8 + c)*PIX + p0 + t];
    for (int oo=0;oo<64;oo++){
        int o = oc + oo;
        float acc = benc[o];
        #pragma unroll
        for (int c=0;c<8;c++) acc = fmaf(xv[c], ws[oo][c], acc);
        g_h[((size_t)b*CEMB + o)*PIX + p0 + t] = acc + pos[(size_t)o*PIX + p0 + t];
    }
}

// ---- fft forward via warp MMA (proven)
__global__ void __launch_bounds__(256) k_fftfwd_mma(){
    __shared__ __align__(16) __nv_bfloat16 Ah[2][128][24], Al[2][128][24];
    __shared__ __align__(16) __nv_bfloat16 Bh[2][16][72],  Bl[2][16][72];
    const int bm0 = blockIdx.x*128;
    const int c0  = blockIdx.y*64;
    const int tid=threadIdx.x, wid=tid>>5, lane=tid&31;
    const int wm=wid>>1, wn=wid&1;
    const int g=lane>>2, tq=lane&3;
    const int ar=tid>>1, akq=(tid&1)*8;
    const int bkr=tid>>4, bnq=(tid&15)*4;
    const int lar=(lane&15), lac=(lane>>4)*8;
    uint32_t aAh = smem_u32(&Ah[0][wm*32 + lar][lac]);
    uint32_t aAl = smem_u32(&Al[0][wm*32 + lar][lac]);
    uint32_t aBh = smem_u32(&Bh[0][lar][wn*32 + lac]);
    uint32_t aBl = smem_u32(&Bl[0][lar][wn*32 + lac]);
    const uint32_t ABUF = 2*128*24, BBUF = 2*16*72;

    float acc[2][4][4];
    #pragma unroll
    for (int i=0;i<2;i++)
        #pragma unroll
        for (int j=0;j<4;j++)
            #pragma unroll
            for (int q=0;q<4;q++) acc[i][j][q]=0.f;

    {
        float4 a0 = *(const float4*)(g_h + (size_t)(bm0+ar)*NLON + akq);
        float4 a1 = *(const float4*)(g_h + (size_t)(bm0+ar)*NLON + akq + 4);
        float av[8]={a0.x,a0.y,a0.z,a0.w,a1.x,a1.y,a1.z,a1.w};
        unsigned short hh[8], ll[8];
        #pragma unroll
        for (int j=0;j<8;j++) bfsplit(av[j], hh[j], ll[j]);
        *(uint4*)&Ah[0][ar][akq] = *(uint4*)hh;
        *(uint4*)&Al[0][ar][akq] = *(uint4*)ll;
        *(uint2*)&Bh[0][bkr][bnq] = *(const uint2*)&g_dfh[(size_t)bkr*NP + c0 + bnq];
        *(uint2*)&Bl[0][bkr][bnq] = *(const uint2*)&g_dfl[(size_t)bkr*NP + c0 + bnq];
    }
    __syncthreads();

    int buf=0;
    for (int s=0;s<16;s++){
        float4 pa0, pa1; uint2 pbh, pbl;
        bool more = (s+1<16);
        if (more){
            int k0=(s+1)*16;
            pa0 = *(const float4*)(g_h + (size_t)(bm0+ar)*NLON + k0 + akq);
            pa1 = *(const float4*)(g_h + (size_t)(bm0+ar)*NLON + k0 + akq + 4);
            pbh = *(const uint2*)&g_dfh[(size_t)(k0+bkr)*NP + c0 + bnq];
            pbl = *(const uint2*)&g_dfl[(size_t)(k0+bkr)*NP + c0 + bnq];
        }
        uint32_t ah[2][4], al[2][4], bh[4][2], bl[4][2];
        uint32_t aoff = buf*ABUF, boff = buf*BBUF;
        LDSM4(ah[0][0],ah[0][1],ah[0][2],ah[0][3], aAh + aoff);
        LDSM4(ah[1][0],ah[1][1],ah[1][2],ah[1][3], aAh + aoff + 16*24*2);
        LDSM4(al[0][0],al[0][1],al[0][2],al[0][3], aAl + aoff);
        LDSM4(al[1][0],al[1][1],al[1][2],al[1][3], aAl + aoff + 16*24*2);
        LDSM4T(bh[0][0],bh[0][1],bh[1][0],bh[1][1], aBh + boff);
        LDSM4T(bh[2][0],bh[2][1],bh[3][0],bh[3][1], aBh + boff + 16*2);
        LDSM4T(bl[0][0],bl[0][1],bl[1][0],bl[1][1], aBl + boff);
        LDSM4T(bl[2][0],bl[2][1],bl[3][0],bl[3][1], aBl + boff + 16*2);
        #pragma unroll
        for (int mt=0;mt<2;mt++)
            #pragma unroll
            for (int nt=0;nt<4;nt++){
                MMA_BF16(acc[mt][nt], ah[mt], bh[nt][0], bh[nt][1]);
                MMA_BF16(acc[mt][nt], ah[mt], bl[nt][0], bl[nt][1]);
                MMA_BF16(acc[mt][nt], al[mt], bh[nt][0], bh[nt][1]);
            }
        if (more){
            int nb = buf^1;
            float av[8]={pa0.x,pa0.y,pa0.z,pa0.w,pa1.x,pa1.y,pa1.z,pa1.w};
            unsigned short hh[8], ll[8];
            #pragma unroll
            for (int j=0;j<8;j++) bfsplit(av[j], hh[j], ll[j]);
            *(uint4*)&Ah[nb][ar][akq] = *(uint4*)hh;
            *(uint4*)&Al[nb][ar][akq] = *(uint4*)ll;
            *(uint2*)&Bh[nb][bkr][bnq] = pbh;
            *(uint2*)&Bl[nb][bkr][bnq] = pbl;
        }
        __syncthreads();
        buf ^= 1;
    }

    #pragma unroll
    for (int mt=0;mt<2;mt++){
        int row = bm0 + wm*32 + mt*16 + g;
        #pragma unroll
        for (int nt=0;nt<4;nt++){
            int m = (c0 + wn*32 + nt*8 + 2*tq) >> 1;
            size_t o = (size_t)m*BCK + row;
            g_Fr[o]   = acc[mt][nt][0];
            g_Fi[o]   = acc[mt][nt][1];
            g_Fr[o+8] = acc[mt][nt][2];
            g_Fi[o+8] = acc[mt][nt][3];
        }
    }
}

// ---- m=128 bin
__global__ void k_fft_m128(){
    int row  = blockIdx.x*8 + (threadIdx.x>>5);
    int lane = threadIdx.x&31;
    const float4* p = (const float4*)(g_h + (size_t)row*NLON);
    float4 x0 = p[lane], x1 = p[lane+32];
    float s = x0.x-x0.y+x0.z-x0.w + x1.x-x1.y+x1.z-x1.w;
    #pragma unroll
    for (int o=16;o;o>>=1) s += __shfl_xor_sync(0xFFFFFFFFu, s, o);
    if (lane==0) g_Fr[(size_t)128*BCK + row] = s * (6.283185307179586f/256.f);
}

// ---- Legendre fwd via warp MMA (proven)
#define LFA 3072
#define LFB 1536
#define LF_FRH 0
#define LF_FRL (2*LFA)
#define LF_FIH (4*LFA)
#define LF_FIL (6*LFA)
#define LF_WH  (8*LFA)
#define LF_WL  (8*LFA + 2*LFB)
#define LF_TOTAL ((8*LFA + 4*LFB)*2)

__global__ void __launch_bounds__(256) k_legfwd_mma(){
    extern __shared__ __nv_bfloat16 lsm[];
    const int m   = blockIdx.z;
    const int bm0 = blockIdx.x*128;
    const int l0  = blockIdx.y*64;
    const float* __restrict__ Ar = g_Fr + (size_t)m*BCK;
    const float* __restrict__ Ai = g_Fi + (size_t)m*BCK;
    const ushort_t* __restrict__ Wh = g_wth + (size_t)m*LL*KLAT;
    const ushort_t* __restrict__ Wl = g_wtl + (size_t)m*LL*KLAT;

    const int tid=threadIdx.x, wid=tid>>5, lane=tid&31;
    const int wm=wid>>1, wn=wid&1;
    const int g=lane>>2, tq=lane&3;
    const int ar=tid>>1, akq=(tid&1)*8;
    const int br=tid>>2, bkq=(tid&3)*4;
    const int lar=(lane&15), lac=(lane>>4)*8;
    const int sel=lane>>3, rowg=lane&7;
    const int bn_add=(sel>>1)*8, bk_add=(sel&1)*8;

    const uint32_t sb = smem_u32(lsm);
    uint32_t aFRH = sb + (LF_FRH + (wm*32+lar)*24 + lac)*2;
    uint32_t aFRL = sb + (LF_FRL + (wm*32+lar)*24 + lac)*2;
    uint32_t aFIH = sb + (LF_FIH + (wm*32+lar)*24 + lac)*2;
    uint32_t aFIL = sb + (LF_FIL + (wm*32+lar)*24 + lac)*2;
    uint32_t aWH0 = sb + (LF_WH + (wn*32 + bn_add + rowg)*24 + bk_add)*2;
    uint32_t aWL0 = sb + (LF_WL + (wn*32 + bn_add + rowg)*24 + bk_add)*2;

    float accR[2][4][4], accI[2][4][4];
    #pragma unroll
    for (int i=0;i<2;i++)
        #pragma unroll
        for (int j=0;j<4;j++)
            #pragma unroll
            for (int q=0;q<4;q++){ accR[i][j][q]=0.f; accI[i][j][q]=0.f; }

    {
        float4 r0 = *(const float4*)(Ar + (size_t)(bm0+ar)*KLAT + akq);
        float4 r1 = *(const float4*)(Ar + (size_t)(bm0+ar)*KLAT + akq + 4);
        float4 i0 = *(const float4*)(Ai + (size_t)(bm0+ar)*KLAT + akq);
        float4 i1 = *(const float4*)(Ai + (size_t)(bm0+ar)*KLAT + akq + 4);
        float rv[8]={r0.x,r0.y,r0.z,r0.w,r1.x,r1.y,r1.z,r1.w};
        float iv[8]={i0.x,i0.y,i0.z,i0.w,i1.x,i1.y,i1.z,i1.w};
        unsigned short rh[8], rl[8], ih[8], il[8];
        #pragma unroll
        for (int j=0;j<8;j++){ bfsplit(rv[j], rh[j], rl[j]); bfsplit(iv[j], ih[j], il[j]); }
        int ao = ar*24 + akq;
        *(uint4*)&lsm[LF_FRH+ao] = *(uint4*)rh;
        *(uint4*)&lsm[LF_FRL+ao] = *(uint4*)rl;
        *(uint4*)&lsm[LF_FIH+ao] = *(uint4*)ih;
        *(uint4*)&lsm[LF_FIL+ao] = *(uint4*)il;
        int bo = br*24 + bkq;
        *(uint2*)&lsm[LF_WH+bo] = *(const uint2*)&Wh[(size_t)(l0+br)*KLAT + bkq];
        *(uint2*)&lsm[LF_WL+bo] = *(const uint2*)&Wl[(size_t)(l0+br)*KLAT + bkq];
    }
    __syncthreads();

    int buf=0;
    for (int s=0;s<8;s++){
        float4 pr0, pr1, pi0, pi1; uint2 pwh, pwl;
        bool more = (s+1<8);
        if (more){
            int k0=(s+1)*16;
            pr0 = *(const float4*)(Ar + (size_t)(bm0+ar)*KLAT + k0 + akq);
            pr1 = *(const float4*)(Ar + (size_t)(bm0+ar)*KLAT + k0 + akq + 4);
            pi0 = *(const float4*)(Ai + (size_t)(bm0+ar)*KLAT + k0 + akq);
            pi1 = *(const float4*)(Ai + (size_t)(bm0+ar)*KLAT + k0 + akq + 4);
            pwh = *(const uint2*)&Wh[(size_t)(l0+br)*KLAT + k0 + bkq];
            pwl = *(const uint2*)&Wl[(size_t)(l0+br)*KLAT + k0 + bkq];
        }
        const uint32_t aof = buf*LFA*2;
        const uint32_t bof = buf*LFB*2;
        uint32_t frh[2][4], frl[2][4], fih[2][4], fil[2][4];
        LDSM4(frh[0][0],frh[0][1],frh[0][2],frh[0][3], aFRH+aof);
        LDSM4(frh[1][0],frh[1][1],frh[1][2],frh[1][3], aFRH+aof+16*24*2);
        LDSM4(frl[0][0],frl[0][1],frl[0][2],frl[0][3], aFRL+aof);
        LDSM4(frl[1][0],frl[1][1],frl[1][2],frl[1][3], aFRL+aof+16*24*2);
        LDSM4(fih[0][0],fih[0][1],fih[0][2],fih[0][3], aFIH+aof);
        LDSM4(fih[1][0],fih[1][1],fih[1][2],fih[1][3], aFIH+aof+16*24*2);
        LDSM4(fil[0][0],fil[0][1],fil[0][2],fil[0][3], aFIL+aof);
        LDSM4(fil[1][0],fil[1][1],fil[1][2],fil[1][3], aFIL+aof+16*24*2);
        uint32_t wh[4][2], wl[4][2];
        LDSM4(wh[0][0],wh[0][1],wh[1][0],wh[1][1], aWH0+bof);
        LDSM4(wh[2][0],wh[2][1],wh[3][0],wh[3][1], aWH0+bof+16*24*2);
        LDSM4(wl[0][0],wl[0][1],wl[1][0],wl[1][1], aWL0+bof);
        LDSM4(wl[2][0],wl[2][1],wl[3][0],wl[3][1], aWL0+bof+16*24*2);
        #pragma unroll
        for (int mt=0;mt<2;mt++)
            #pragma unroll
            for (int nt=0;nt<4;nt++){
                MMA_BF16(accR[mt][nt], frh[mt], wh[nt][0], wh[nt][1]);
                MMA_BF16(accR[mt][nt], frh[mt], wl[nt][0], wl[nt][1]);
                MMA_BF16(accR[mt][nt], frl[mt], wh[nt][0], wh[nt][1]);
                MMA_BF16(accI[mt][nt], fih[mt], wh[nt][0], wh[nt][1]);
                MMA_BF16(accI[mt][nt], fih[mt], wl[nt][0], wl[nt][1]);
                MMA_BF16(accI[mt][nt], fil[mt], wh[nt][0], wh[nt][1]);
            }
        if (more){
            int nb = buf^1;
            float rv[8]={pr0.x,pr0.y,pr0.z,pr0.w,pr1.x,pr1.y,pr1.z,pr1.w};
            float iv[8]={pi0.x,pi0.y,pi0.z,pi0.w,pi1.x,pi1.y,pi1.z,pi1.w};
            unsigned short rh[8], rl[8], ih[8], il[8];
            #pragma unroll
            for (int j=0;j<8;j++){ bfsplit(rv[j], rh[j], rl[j]); bfsplit(iv[j], ih[j], il[j]); }
            int ao = nb*LFA + ar*24 + akq;
            *(uint4*)&lsm[LF_FRH+ao] = *(uint4*)rh;
            *(uint4*)&lsm[LF_FRL+ao] = *(uint4*)rl;
            *(uint4*)&lsm[LF_FIH+ao] = *(uint4*)ih;
            *(uint4*)&lsm[LF_FIL+ao] = *(uint4*)il;
            int bo = nb*LFB + br*24 + bkq;
            *(uint2*)&lsm[LF_WH+bo] = pwh;
            *(uint2*)&lsm[LF_WL+bo] = pwl;
        }
        __syncthreads();
        buf ^= 1;
    }

    #pragma unroll
    for (int mt=0;mt<2;mt++){
        int row = bm0 + wm*32 + mt*16 + g;
        #pragma unroll
        for (int nt=0;nt<4;nt++){
            int lcol = l0 + wn*32 + nt*8 + 2*tq;
            #pragma unroll
            for (int q=0;q<2;q++){
                int l = lcol + q;
                int r0 = row, r1 = row+8;
                size_t o0 = (((size_t)l*BB + (r0>>8))*MM + m)*CEMB + (r0&255);
                size_t o1 = (((size_t)l*BB + (r1>>8))*MM + m)*CEMB + (r1&255);
                g_Dr[o0] = accR[mt][nt][q];
                g_Di[o0] = accI[mt][nt][q];
                g_Dr[o1] = accR[mt][nt][2+q];
                g_Di[o1] = accI[mt][nt][2+q];
            }
        }
    }
}

// ---- dhconv via warp MMA: rows 0..255 only (no guards); tail handles 256-257
#define DA_BUF 3072
#define DB_BUF 1152
#define DOF_DRH 0
#define DOF_DRL (2*DA_BUF)
#define DOF_DIH (4*DA_BUF)
#define DOF_DIL (6*DA_BUF)
#define DOF_BRH (8*DA_BUF)
#define DOF_BRL (8*DA_BUF + 2*DB_BUF)
#define DOF_BIH (8*DA_BUF + 4*DB_BUF)
#define DOF_BIL (8*DA_BUF + 6*DB_BUF)
#define DOF_BNH (8*DA_BUF + 8*DB_BUF)
#define DOF_BNL (8*DA_BUF + 10*DB_BUF)
#define DSM_TOTAL ((8*DA_BUF + 12*DB_BUF)*2)

__global__ void __launch_bounds__(256) k_dhconv_mma(int layer){
    extern __shared__ __nv_bfloat16 dsm[];
    const int l   = blockIdx.z;
    const int bm0 = blockIdx.x*128;
    const int o0  = blockIdx.y*64;
    const float* __restrict__ Ar = g_Dr + (size_t)l*RC;
    const float* __restrict__ Ai = g_Di + (size_t)l*RC;
    const size_t wbase = ((size_t)(layer*LL + l))*CEMB*CEMB;

    const int tid=threadIdx.x, wid=tid>>5, lane=tid&31;
    const int wm=wid>>1, wn=wid&1;
    const int g=lane>>2, tq=lane&3;
    const int ar=tid>>1, akq=(tid&1)*8;
    const int bkr=tid>>4, bnq=(tid&15)*4;
    const int lar=(lane&15), lac=(lane>>4)*8;

    const uint32_t sb = smem_u32(dsm);
    uint32_t aDRH = sb + (DOF_DRH + (wm*32+lar)*24 + lac)*2;
    uint32_t aDRL = sb + (DOF_DRL + (wm*32+lar)*24 + lac)*2;
    uint32_t aDIH = sb + (DOF_DIH + (wm*32+lar)*24 + lac)*2;
    uint32_t aDIL = sb + (DOF_DIL + (wm*32+lar)*24 + lac)*2;
    uint32_t aBRH = sb + (DOF_BRH + lar*72 + wn*32 + lac)*2;
    uint32_t aBRL = sb + (DOF_BRL + lar*72 + wn*32 + lac)*2;
    uint32_t aBIH = sb + (DOF_BIH + lar*72 + wn*32 + lac)*2;
    uint32_t aBIL = sb + (DOF_BIL + lar*72 + wn*32 + lac)*2;
    uint32_t aBNH = sb + (DOF_BNH + lar*72 + wn*32 + lac)*2;
    uint32_t aBNL = sb + (DOF_BNL + lar*72 + wn*32 + lac)*2;

    float accR[2][4][4], accI[2][4][4];
    #pragma unroll
    for (int i=0;i<2;i++)
        #pragma unroll
        for (int j=0;j<4;j++)
            #pragma unroll
            for (int q=0;q<4;q++){ accR[i][j][q]=0.f; accI[i][j][q]=0.f; }

    const int arow = bm0 + ar;

    {
        float4 r0 = *(const float4*)(Ar + (size_t)arow*CEMB + akq);
        float4 r1 = *(const float4*)(Ar + (size_t)arow*CEMB + akq + 4);
        float4 i0 = *(const float4*)(Ai + (size_t)arow*CEMB + akq);
        float4 i1 = *(const float4*)(Ai + (size_t)arow*CEMB + akq + 4);
        float rv[8]={r0.x,r0.y,r0.z,r0.w,r1.x,r1.y,r1.z,r1.w};
        float iv[8]={i0.x,i0.y,i0.z,i0.w,i1.x,i1.y,i1.z,i1.w};
        unsigned short rh[8], rl[8], ih[8], il[8];
        #pragma unroll
        for (int j=0;j<8;j++){ bfsplit(rv[j], rh[j], rl[j]); bfsplit(iv[j], ih[j], il[j]); }
        int ao = ar*24 + akq;
        *(uint4*)&dsm[DOF_DRH+ao] = *(uint4*)rh;
        *(uint4*)&dsm[DOF_DRL+ao] = *(uint4*)rl;
        *(uint4*)&dsm[DOF_DIH+ao] = *(uint4*)ih;
        *(uint4*)&dsm[DOF_DIL+ao] = *(uint4*)il;
        size_t wb = wbase + (size_t)bkr*CEMB + o0 + bnq;
        uint2 wrh2 = *(const uint2*)&g_Brh[wb];
        uint2 wrl2 = *(const uint2*)&g_Brl[wb];
        uint2 wih2 = *(const uint2*)&g_Bih[wb];
        uint2 wil2 = *(const uint2*)&g_Bil[wb];
        uint2 wnh2 = make_uint2(wih2.x^0x80008000u, wih2.y^0x80008000u);
        uint2 wnl2 = make_uint2(wil2.x^0x80008000u, wil2.y^0x80008000u);
        int bo = bkr*72 + bnq;
        *(uint2*)&dsm[DOF_BRH+bo] = wrh2;
        *(uint2*)&dsm[DOF_BRL+bo] = wrl2;
        *(uint2*)&dsm[DOF_BIH+bo] = wih2;
        *(uint2*)&dsm[DOF_BIL+bo] = wil2;
        *(uint2*)&dsm[DOF_BNH+bo] = wnh2;
        *(uint2*)&dsm[DOF_BNL+bo] = wnl2;
    }
    __syncthreads();

    int buf=0;
    for (int s=0;s<16;s++){
        float4 pr0, pr1, pi0, pi1;
        uint2 pwrh, pwrl, pwih, pwil;
        bool more = (s+1<16);
        if (more){
            int k0=(s+1)*16;
            pr0 = *(const float4*)(Ar + (size_t)arow*CEMB + k0 + akq);
            pr1 = *(const float4*)(Ar + (size_t)arow*CEMB + k0 + akq + 4);
            pi0 = *(const float4*)(Ai + (size_t)arow*CEMB + k0 + akq);
            pi1 = *(const float4*)(Ai + (size_t)arow*CEMB + k0 + akq + 4);
            size_t wb = wbase + (size_t)(k0+bkr)*CEMB + o0 + bnq;
            pwrh = *(const uint2*)&g_Brh[wb];
            pwrl = *(const uint2*)&g_Brl[wb];
            pwih = *(const uint2*)&g_Bih[wb];
            pwil = *(const uint2*)&g_Bil[wb];
        }
        const uint32_t aof = buf*DA_BUF*2;
        const uint32_t bof = buf*DB_BUF*2;
        uint32_t drh[2][4], drl[2][4], dih[2][4], dil[2][4];
        LDSM4(drh[0][0],drh[0][1],drh[0][2],drh[0][3], aDRH+aof);
        LDSM4(drh[1][0],drh[1][1],drh[1][2],drh[1][3], aDRH+aof+16*24*2);
        LDSM4(drl[0][0],drl[0][1],drl[0][2],drl[0][3], aDRL+aof);
        LDSM4(drl[1][0],drl[1][1],drl[1][2],drl[1][3], aDRL+aof+16*24*2);
        LDSM4(dih[0][0],dih[0][1],dih[0][2],dih[0][3], aDIH+aof);
        LDSM4(dih[1][0],dih[1][1],dih[1][2],dih[1][3], aDIH+aof+16*24*2);
        LDSM4(dil[0][0],dil[0][1],dil[0][2],dil[0][3], aDIL+aof);
        LDSM4(dil[1][0],dil[1][1],dil[1][2],dil[1][3], aDIL+aof+16*24*2);
        uint32_t brh[4][2], brl[4][2], bih[4][2], bil[4][2], bnh[4][2], bnl[4][2];
        LDSM4T(brh[0][0],brh[0][1],brh[1][0],brh[1][1], aBRH+bof);
        LDSM4T(brh[2][0],brh[2][1],brh[3][0],brh[3][1], aBRH+bof+16*2);
        LDSM4T(brl[0][0],brl[0][1],brl[1][0],brl[1][1], aBRL+bof);
        LDSM4T(brl[2][0],brl[2][1],brl[3][0],brl[3][1], aBRL+bof+16*2);
        LDSM4T(bih[0][0],bih[0][1],bih[1][0],bih[1][1], aBIH+bof);
        LDSM4T(bih[2][0],bih[2][1],bih[3][0],bih[3][1], aBIH+bof+16*2);
        LDSM4T(bil[0][0],bil[0][1],bil[1][0],bil[1][1], aBIL+bof);
        LDSM4T(bil[2][0],bil[2][1],bil[3][0],bil[3][1], aBIL+bof+16*2);
        LDSM4T(bnh[0][0],bnh[0][1],bnh[1][0],bnh[1][1], aBNH+bof);
        LDSM4T(bnh[2][0],bnh[2][1],bnh[3][0],bnh[3][1], aBNH+bof+16*2);
        LDSM4T(bnl[0][0],bnl[0][1],bnl[1][0],bnl[1][1], aBNL+bof);
        LDSM4T(bnl[2][0],bnl[2][1],bnl[3][0],bnl[3][1], aBNL+bof+16*2);
        #pragma unroll
        for (int mt=0;mt<2;mt++)
            #pragma unroll
            for (int nt=0;nt<4;nt++){
                MMA_BF16(accR[mt][nt], drh[mt], brh[nt][0], brh[nt][1]);
                MMA_BF16(accR[mt][nt], drh[mt], brl[nt][0], brl[nt][1]);
                MMA_BF16(accR[mt][nt], drl[mt], brh[nt][0], brh[nt][1]);
                MMA_BF16(accR[mt][nt], dih[mt], bnh[nt][0], bnh[nt][1]);
                MMA_BF16(accR[mt][nt], dih[mt], bnl[nt][0], bnl[nt][1]);
                MMA_BF16(accR[mt][nt], dil[mt], bnh[nt][0], bnh[nt][1]);
                MMA_BF16(accI[mt][nt], drh[mt], bih[nt][0], bih[nt][1]);
                MMA_BF16(accI[mt][nt], drh[mt], bil[nt][0], bil[nt][1]);
                MMA_BF16(accI[mt][nt], drl[mt], bih[nt][0], bih[nt][1]);
                MMA_BF16(accI[mt][nt], dih[mt], brh[nt][0], brh[nt][1]);
                MMA_BF16(accI[mt][nt], dih[mt], brl[nt][0], brl[nt][1]);
                MMA_BF16(accI[mt][nt], dil[mt], brh[nt][0], brh[nt][1]);
            }
        if (more){
            int nb = buf^1;
            float rv[8]={pr0.x,pr0.y,pr0.z,pr0.w,pr1.x,pr1.y,pr1.z,pr1.w};
            float iv[8]={pi0.x,pi0.y,pi0.z,pi0.w,pi1.x,pi1.y,pi1.z,pi1.w};
            unsigned short rh[8], rl[8], ih[8], il[8];
            #pragma unroll
            for (int j=0;j<8;j++){ bfsplit(rv[j], rh[j], rl[j]); bfsplit(iv[j], ih[j], il[j]); }
            int ao = nb*DA_BUF + ar*24 + akq;
            *(uint4*)&dsm[DOF_DRH+ao] = *(uint4*)rh;
            *(uint4*)&dsm[DOF_DRL+ao] = *(uint4*)rl;
            *(uint4*)&dsm[DOF_DIH+ao] = *(uint4*)ih;
            *(uint4*)&dsm[DOF_DIL+ao] = *(uint4*)il;
            uint2 wnh2 = make_uint2(pwih.x^0x80008000u, pwih.y^0x80008000u);
            uint2 wnl2 = make_uint2(pwil.x^0x80008000u, pwil.y^0x80008000u);
            int bo = nb*DB_BUF + bkr*72 + bnq;
            *(uint2*)&dsm[DOF_BRH+bo] = pwrh;
            *(uint2*)&dsm[DOF_BRL+bo] = pwrl;
            *(uint2*)&dsm[DOF_BIH+bo] = pwih;
            *(uint2*)&dsm[DOF_BIL+bo] = pwil;
            *(uint2*)&dsm[DOF_BNH+bo] = wnh2;
            *(uint2*)&dsm[DOF_BNL+bo] = wnl2;
        }
        __syncthreads();
        buf ^= 1;
    }

    #pragma unroll
    for (int mt=0;mt<2;mt++){
        int row = bm0 + wm*32 + mt*16 + g;
        #pragma unroll
        for (int nt=0;nt<4;nt++){
            int col = o0 + wn*32 + nt*8 + 2*tq;
            size_t o = (size_t)l*RC + (size_t)row*CEMB + col;
            *(float2*)(g_Er+o) = make_float2(accR[mt][nt][0], accR[mt][nt][1]);
            *(float2*)(g_Ei+o) = make_float2(accI[mt][nt][0], accI[mt][nt][1]);
            size_t o2 = o + (size_t)8*CEMB;
            *(float2*)(g_Er+o2) = make_float2(accR[mt][nt][2], accR[mt][nt][3]);
            *(float2*)(g_Ei+o2) = make_float2(accI[mt][nt][2], accI[mt][nt][3]);
        }
    }
}

// ---- dhconv tail: rows 256,257 (complex mat-vec per l)
__global__ void __launch_bounds__(256) k_dhconv_tail(int layer){
    __shared__ float dr[2][CEMB], di[2][CEMB];
    const int l = blockIdx.x;
    const int o = threadIdx.x;
    const size_t abase = (size_t)l*RC + (size_t)256*CEMB;
    dr[0][o] = g_Dr[abase + o];
    di[0][o] = g_Di[abase + o];
    dr[1][o] = g_Dr[abase + CEMB + o];
    di[1][o] = g_Di[abase + CEMB + o];
    __syncthreads();
    const size_t wbase = ((size_t)(layer*LL + l))*CEMB*CEMB;
    float er0=0.f, ei0=0.f, er1=0.f, ei1=0.f;
    for (int i=0;i<CEMB;i++){
        size_t wb = wbase + (size_t)i*CEMB + o;
        float wr = bf2f(g_Brh[wb]) + bf2f(g_Brl[wb]);
        float wi = bf2f(g_Bih[wb]) + bf2f(g_Bil[wb]);
        float r0=dr[0][i], i0=di[0][i], r1=dr[1][i], i1=di[1][i];
        er0 = fmaf(r0, wr, er0); er0 = fmaf(-i0, wi, er0);
        ei0 = fmaf(r0, wi, ei0); ei0 = fmaf( i0, wr, ei0);
        er1 = fmaf(r1, wr, er1); er1 = fmaf(-i1, wi, er1);
        ei1 = fmaf(r1, wi, ei1); ei1 = fmaf( i1, wr, ei1);
    }
    g_Er[abase + o] = er0;        g_Ei[abase + o] = ei0;
    g_Er[abase + CEMB + o] = er1; g_Ei[abase + CEMB + o] = ei1;
}

// ---- Legendre bwd via warp MMA (proven)
#define LBA 2176
#define LBB 1152
#define LB_ERH 0
#define LB_ERL (2*LBA)
#define LB_EIH (4*LBA)
#define LB_EIL (6*LBA)
#define LB_WH  (8*LBA)
#define LB_WL  (8*LBA + 2*LBB)

__global__ void __launch_bounds__(256) k_legbwd_mma(){
    __shared__ __align__(16) __nv_bfloat16 lsm[8*LBA + 4*LBB];
    const int m   = blockIdx.z;
    const int bm0 = blockIdx.x*128;
    const int k0n = blockIdx.y*64;
    const int bT = bm0>>8, c0 = bm0&255;
    const size_t abase = ((size_t)bT*MM + m)*CEMB + c0;
    const ushort_t* __restrict__ Wh = g_iwh + (size_t)m*LL*KLAT;
    const ushort_t* __restrict__ Wl = g_iwl + (size_t)m*LL*KLAT;

    const int tid=threadIdx.x, wid=tid>>5, lane=tid&31;
    const int wm=wid>>1, wn=wid&1;
    const int g=lane>>2, tq=lane&3;
    const int la=tid>>4, cq=(tid&15)*8;
    const int bkr=tid>>4, bnq=(tid&15)*4;
    const int lar=(lane&15), lac=(lane>>4)*8;
    const int sel=lane>>3, rowg=lane&7;
    const int m_add=(sel&1)*8, k_add=(sel>>1)*8;

    const uint32_t sb = smem_u32(lsm);
    uint32_t aERH = sb + (LB_ERH + (k_add+rowg)*136 + wm*32 + m_add)*2;
    uint32_t aERL = sb + (LB_ERL + (k_add+rowg)*136 + wm*32 + m_add)*2;
    uint32_t aEIH = sb + (LB_EIH + (k_add+rowg)*136 + wm*32 + m_add)*2;
    uint32_t aEIL = sb + (LB_EIL + (k_add+rowg)*136 + wm*32 + m_add)*2;
    uint32_t aWH  = sb + (LB_WH + lar*72 + wn*32 + lac)*2;
    uint32_t aWL  = sb + (LB_WL + lar*72 + wn*32 + lac)*2;

    float accR[2][4][4], accI[2][4][4];
    #pragma unroll
    for (int i=0;i<2;i++)
        #pragma unroll
        for (int j=0;j<4;j++)
            #pragma unroll
            for (int q=0;q<4;q++){ accR[i][j][q]=0.f; accI[i][j][q]=0.f; }

    {
        float4 r0 = *(const float4*)(g_Er + (size_t)la*RC + abase + cq);
        float4 r1 = *(const float4*)(g_Er + (size_t)la*RC + abase + cq + 4);
        float4 i0 = *(const float4*)(g_Ei + (size_t)la*RC + abase + cq);
        float4 i1 = *(const float4*)(g_Ei + (size_t)la*RC + abase + cq + 4);
        float rv[8]={r0.x,r0.y,r0.z,r0.w,r1.x,r1.y,r1.z,r1.w};
        float iv[8]={i0.x,i0.y,i0.z,i0.w,i1.x,i1.y,i1.z,i1.w};
        unsigned short rh[8], rl[8], ih[8], il[8];
        #pragma unroll
        for (int j=0;j<8;j++){ bfsplit(rv[j], rh[j], rl[j]); bfsplit(iv[j], ih[j], il[j]); }
        int ao = la*136 + cq;
        *(uint4*)&lsm[LB_ERH+ao] = *(uint4*)rh;
        *(uint4*)&lsm[LB_ERL+ao] = *(uint4*)rl;
        *(uint4*)&lsm[LB_EIH+ao] = *(uint4*)ih;
        *(uint4*)&lsm[LB_EIL+ao] = *(uint4*)il;
        int bo = bkr*72 + bnq;
        *(uint2*)&lsm[LB_WH+bo] = *(const uint2*)&Wh[(size_t)bkr*KLAT + k0n + bnq];
        *(uint2*)&lsm[LB_WL+bo] = *(const uint2*)&Wl[(size_t)bkr*KLAT + k0n + bnq];
    }
    __syncthreads();

    int buf=0;
    for (int s=0;s<8;s++){
        float4 pr0, pr1, pi0, pi1; uint2 pwh, pwl;
        bool more = (s+1<8);
        if (more){
            int l0=(s+1)*16;
            pr0 = *(const float4*)(g_Er + (size_t)(l0+la)*RC + abase + cq);
            pr1 = *(const float4*)(g_Er + (size_t)(l0+la)*RC + abase + cq + 4);
            pi0 = *(const float4*)(g_Ei + (size_t)(l0+la)*RC + abase + cq);
            pi1 = *(const float4*)(g_Ei + (size_t)(l0+la)*RC + abase + cq + 4);
            pwh = *(const uint2*)&Wh[(size_t)(l0+bkr)*KLAT + k0n + bnq];
            pwl = *(const uint2*)&Wl[(size_t)(l0+bkr)*KLAT + k0n + bnq];
        }
        const uint32_t aof = buf*LBA*2;
        const uint32_t bof = buf*LBB*2;
        uint32_t erh[2][4], erl[2][4], eih[2][4], eil[2][4];
        LDSM4T(erh[0][0],erh[0][1],erh[0][2],erh[0][3], aERH+aof);
        LDSM4T(erh[1][0],erh[1][1],erh[1][2],erh[1][3], aERH+aof+16*2);
        LDSM4T(erl[0][0],erl[0][1],erl[0][2],erl[0][3], aERL+aof);
        LDSM4T(erl[1][0],erl[1][1],erl[1][2],erl[1][3], aERL+aof+16*2);
        LDSM4T(eih[0][0],eih[0][1],eih[0][2],eih[0][3], aEIH+aof);
        LDSM4T(eih[1][0],eih[1][1],eih[1][2],eih[1][3], aEIH+aof+16*2);
        LDSM4T(eil[0][0],eil[0][1],eil[0][2],eil[0][3], aEIL+aof);
        LDSM4T(eil[1][0],eil[1][1],eil[1][2],eil[1][3], aEIL+aof+16*2);
        uint32_t wh[4][2], wl[4][2];
        LDSM4T(wh[0][0],wh[0][1],wh[1][0],wh[1][1], aWH+bof);
        LDSM4T(wh[2][0],wh[2][1],wh[3][0],wh[3][1], aWH+bof+16*2);
        LDSM4T(wl[0][0],wl[0][1],wl[1][0],wl[1][1], aWL+bof);
        LDSM4T(wl[2][0],wl[2][1],wl[3][0],wl[3][1], aWL+bof+16*2);
        #pragma unroll
        for (int mt=0;mt<2;mt++)
            #pragma unroll
            for (int nt=0;nt<4;nt++){
                MMA_BF16(accR[mt][nt], erh[mt], wh[nt][0], wh[nt][1]);
                MMA_BF16(accR[mt][nt], erh[mt], wl[nt][0], wl[nt][1]);
                MMA_BF16(accR[mt][nt], erl[mt], wh[nt][0], wh[nt][1]);
                MMA_BF16(accI[mt][nt], eih[mt], wh[nt][0], wh[nt][1]);
                MMA_BF16(accI[mt][nt], eih[mt], wl[nt][0], wl[nt][1]);
                MMA_BF16(accI[mt][nt], eil[mt], wh[nt][0], wh[nt][1]);
            }
        if (more){
            int nb = buf^1;
            float rv[8]={pr0.x,pr0.y,pr0.z,pr0.w,pr1.x,pr1.y,pr1.z,pr1.w};
            float iv[8]={pi0.x,pi0.y,pi0.z,pi0.w,pi1.x,pi1.y,pi1.z,pi1.w};
            unsigned short rh[8], rl[8], ih[8], il[8];
            #pragma unroll
            for (int j=0;j<8;j++){ bfsplit(rv[j], rh[j], rl[j]); bfsplit(iv[j], ih[j], il[j]); }
            int ao = nb*LBA + la*136 + cq;
            *(uint4*)&lsm[LB_ERH+ao] = *(uint4*)rh;
            *(uint4*)&lsm[LB_ERL+ao] = *(uint4*)rl;
            *(uint4*)&lsm[LB_EIH+ao] = *(uint4*)ih;
            *(uint4*)&lsm[LB_EIL+ao] = *(uint4*)il;
            int bo = nb*LBB + bkr*72 + bnq;
            *(uint2*)&lsm[LB_WH+bo] = pwh;
            *(uint2*)&lsm[LB_WL+bo] = pwl;
        }
        __syncthreads();
        buf ^= 1;
    }

    #pragma unroll
    for (int mt=0;mt<2;mt++){
        int row = bm0 + wm*32 + mt*16 + g;
        #pragma unroll
        for (int nt=0;nt<4;nt++){
            int col = k0n + wn*32 + nt*8 + 2*tq;
            size_t o0 = (size_t)m*BCK + (size_t)row*KLAT + col;
            size_t o1 = o0 + (size_t)8*KLAT;
            *(float2*)(g_Yr+o0) = make_float2(accR[mt][nt][0], accR[mt][nt][1]);
            *(float2*)(g_Yi+o0) = make_float2(accI[mt][nt][0], accI[mt][nt][1]);
            *(float2*)(g_Yr+o1) = make_float2(accR[mt][nt][2], accR[mt][nt][3]);
            *(float2*)(g_Yi+o1) = make_float2(accI[mt][nt][2], accI[mt][nt][3]);
        }
    }
}

// ---- fft inverse via warp MMA (proven)
#define FI_AH 0
#define FI_AL (2*LBA)
#define FI_BH (4*LBA)
#define FI_BL (4*LBA + 2*LBB)

__global__ void __launch_bounds__(256) k_fftinv_mma(){
    __shared__ __align__(16) __nv_bfloat16 fsm[4*LBA + 4*LBB];
    const int bm0 = blockIdx.x*128;
    const int n0  = blockIdx.y*64;
    const int tid=threadIdx.x, wid=tid>>5, lane=tid&31;
    const int wm=wid>>1, wn=wid&1;
    const int g=lane>>2, tq=lane&3;
    const int la=tid>>4, rq=(tid&15)*8;
    const int bkr=tid>>4, bnq=(tid&15)*4;
    const int lar=(lane&15), lac=(lane>>4)*8;
    const int sel=lane>>3, rowg=lane&7;
    const int m_add=(sel&1)*8, k_add=(sel>>1)*8;

    const uint32_t sb = smem_u32(fsm);
    uint32_t aAH = sb + (FI_AH + (k_add+rowg)*136 + wm*32 + m_add)*2;
    uint32_t aAL = sb + (FI_AL + (k_add+rowg)*136 + wm*32 + m_add)*2;
    uint32_t aBH = sb + (FI_BH + lar*72 + wn*32 + lac)*2;
    uint32_t aBL = sb + (FI_BL + lar*72 + wn*32 + lac)*2;

    float acc[2][4][4];
    #pragma unroll
    for (int i=0;i<2;i++)
        #pragma unroll
        for (int j=0;j<4;j++)
            #pragma unroll
            for (int q=0;q<4;q++) acc[i][j][q]=0.f;

    {
        const float* arr = (la&1) ? g_Yi : g_Yr;
        float4 a0 = *(const float4*)(arr + (size_t)(la>>1)*BCK + bm0 + rq);
        float4 a1 = *(const float4*)(arr + (size_t)(la>>1)*BCK + bm0 + rq + 4);
        float av[8]={a0.x,a0.y,a0.z,a0.w,a1.x,a1.y,a1.z,a1.w};
        unsigned short hh[8], ll[8];
        #pragma unroll
        for (int j=0;j<8;j++) bfsplit(av[j], hh[j], ll[j]);
        int ao = la*136 + rq;
        *(uint4*)&fsm[FI_AH+ao] = *(uint4*)hh;
        *(uint4*)&fsm[FI_AL+ao] = *(uint4*)ll;
        int bo = bkr*72 + bnq;
        *(uint2*)&fsm[FI_BH+bo] = *(const uint2*)&g_dih[(size_t)bkr*NLON + n0 + bnq];
        *(uint2*)&fsm[FI_BL+bo] = *(const uint2*)&g_dil[(size_t)bkr*NLON + n0 + bnq];
    }
    __syncthreads();

    int buf=0;
    const int NST=17;
    for (int s=0;s<NST;s++){
        float4 pa0, pa1; uint2 pbh, pbl;
        bool more = (s+1<NST);
        if (more){
            int c0=(s+1)*16;
            int cm = c0 + la;
            const float* arr = (cm&1) ? g_Yi : g_Yr;
            pa0 = *(const float4*)(arr + (size_t)(cm>>1)*BCK + bm0 + rq);
            pa1 = *(const float4*)(arr + (size_t)(cm>>1)*BCK + bm0 + rq + 4);
            pbh = *(const uint2*)&g_dih[(size_t)(c0+bkr)*NLON + n0 + bnq];
            pbl = *(const uint2*)&g_dil[(size_t)(c0+bkr)*NLON + n0 + bnq];
        }
        const uint32_t aof = buf*LBA*2;
        const uint32_t bof = buf*LBB*2;
        uint32_t ah[2][4], al[2][4], bh[4][2], bl[4][2];
        LDSM4T(ah[0][0],ah[0][1],ah[0][2],ah[0][3], aAH+aof);
        LDSM4T(ah[1][0],ah[1][1],ah[1][2],ah[1][3], aAH+aof+16*2);
        LDSM4T(al[0][0],al[0][1],al[0][2],al[0][3], aAL+aof);
        LDSM4T(al[1][0],al[1][1],al[1][2],al[1][3], aAL+aof+16*2);
        LDSM4T(bh[0][0],bh[0][1],bh[1][0],bh[1][1], aBH+bof);
        LDSM4T(bh[2][0],bh[2][1],bh[3][0],bh[3][1], aBH+bof+16*2);
        LDSM4T(bl[0][0],bl[0][1],bl[1][0],bl[1][1], aBL+bof);
        LDSM4T(bl[2][0],bl[2][1],bl[3][0],bl[3][1], aBL+bof+16*2);
        #pragma unroll
        for (int mt=0;mt<2;mt++)
            #pragma unroll
            for (int nt=0;nt<4;nt++){
                MMA_BF16(acc[mt][nt], ah[mt], bh[nt][0], bh[nt][1]);
                MMA_BF16(acc[mt][nt], ah[mt], bl[nt][0], bl[nt][1]);
                MMA_BF16(acc[mt][nt], al[mt], bh[nt][0], bh[nt][1]);
            }
        if (more){
            int nb = buf^1;
            float av[8]={pa0.x,pa0.y,pa0.z,pa0.w,pa1.x,pa1.y,pa1.z,pa1.w};
            unsigned short hh[8], ll[8];
            #pragma unroll
            for (int j=0;j<8;j++) bfsplit(av[j], hh[j], ll[j]);
            int ao = nb*LBA + la*136 + rq;
            *(uint4*)&fsm[FI_AH+ao] = *(uint4*)hh;
            *(uint4*)&fsm[FI_AL+ao] = *(uint4*)ll;
            int bo = nb*LBB + bkr*72 + bnq;
            *(uint2*)&fsm[FI_BH+bo] = pbh;
            *(uint2*)&fsm[FI_BL+bo] = pbl;
        }
        __syncthreads();
        buf ^= 1;
    }

    #pragma unroll
    for (int mt=0;mt<2;mt++){
        int row = bm0 + wm*32 + mt*16 + g;
        #pragma unroll
        for (int nt=0;nt<4;nt++){
            int col = n0 + wn*32 + nt*8 + 2*tq;
            size_t o0 = (size_t)row*NLON + col;
            size_t o1 = o0 + (size_t)8*NLON;
            float2 h0 = *(const float2*)(g_h+o0);
            float2 h1 = *(const float2*)(g_h+o1);
            *(float2*)(g_h+o0) = make_float2(gelu_tanh(acc[mt][nt][0])+h0.x,
                                             gelu_tanh(acc[mt][nt][1])+h0.y);
            *(float2*)(g_h+o1) = make_float2(gelu_tanh(acc[mt][nt][2])+h1.x,
                                             gelu_tanh(acc[mt][nt][3])+h1.y);
        }
    }
}

// ---- warp-MMA bf16 MLP (proven)
__global__ void __launch_bounds__(256) k_mlp_mma(
    int mode, int K, const float* __restrict__ A, const float* __restrict__ bias)
{
    __shared__ __align__(16) __nv_bfloat16 Ah[2][128][24], Al[2][128][24];
    __shared__ __align__(16) __nv_bfloat16 Bh[2][16][72],  Bl[2][16][72];
    const int pix0 = blockIdx.x*64;
    const int m0   = blockIdx.y*128;
    const int bz   = blockIdx.z;
    const float* __restrict__ Bg = (mode ? g_t : g_h) + (size_t)bz*K*PIX;
    float* __restrict__ Cg       = (mode ? g_h : g_t) + (size_t)bz*(mode?CEMB:HID)*PIX;

    const int tid=threadIdx.x, wid=tid>>5, lane=tid&31;
    const int wm=wid>>1, wn=wid&1;
    const int g=lane>>2, tq=lane&3;
    const int ar=tid>>1, akq=(tid&1)*8;
    const int bkr=tid>>4, bnq=(tid&15)*4;

    const int lar = (lane&15), lac = (lane>>4)*8;
    uint32_t aAh = smem_u32(&Ah[0][wm*32 + lar][lac]);
    uint32_t aAl = smem_u32(&Al[0][wm*32 + lar][lac]);
    uint32_t aB0h = smem_u32(&Bh[0][lar][wn*32 + lac]);
    uint32_t aB0l = smem_u32(&Bl[0][lar][wn*32 + lac]);
    const uint32_t ABUF = sizeof(__nv_bfloat16)*128*24;
    const uint32_t BBUF = sizeof(__nv_bfloat16)*16*72;

    float acc[2][4][4];
    #pragma unroll
    for (int i=0;i<2;i++)
        #pragma unroll
        for (int j=0;j<4;j++)
            #pragma unroll
            for (int q=0;q<4;q++) acc[i][j][q]=0.f;

    {
        float4 a0 = *(const float4*)(A + (size_t)(m0+ar)*K + akq);
        float4 a1 = *(const float4*)(A + (size_t)(m0+ar)*K + akq + 4);
        float4 b0 = *(const float4*)(Bg + (size_t)bkr*PIX + pix0 + bnq);
        float av[8]={a0.x,a0.y,a0.z,a0.w,a1.x,a1.y,a1.z,a1.w};
        unsigned short hh[8], ll[8];
        #pragma unroll
        for (int j=0;j<8;j++) bfsplit(av[j], hh[j], ll[j]);
        *(uint4*)&Ah[0][ar][akq] = *(uint4*)hh;
        *(uint4*)&Al[0][ar][akq] = *(uint4*)ll;
        float bv[4]={b0.x,b0.y,b0.z,b0.w};
        unsigned short bh4[4], bl4[4];
        #pragma unroll
        for (int j=0;j<4;j++) bfsplit(bv[j], bh4[j], bl4[j]);
        *(uint2*)&Bh[0][bkr][bnq] = *(uint2*)bh4;
        *(uint2*)&Bl[0][bkr][bnq] = *(uint2*)bl4;
    }
    __syncthreads();

    const int nstep = K>>4;
    int buf=0;
    for (int s=0;s<nstep;s++){
        float4 pa0, pa1, pb0;
        bool more = (s+1<nstep);
        if (more){
            int k0=(s+1)*16;
            pa0 = *(const float4*)(A + (size_t)(m0+ar)*K + k0 + akq);
            pa1 = *(const float4*)(A + (size_t)(m0+ar)*K + k0 + akq + 4);
            pb0 = *(const float4*)(Bg + (size_t)(k0+bkr)*PIX + pix0 + bnq);
        }
        uint32_t ah[2][4], al[2][4], bh[4][2], bl[4][2];
        uint32_t aoff = buf*ABUF;
        uint32_t boff = buf*BBUF;
        LDSM4(ah[0][0],ah[0][1],ah[0][2],ah[0][3], aAh + aoff);
        LDSM4(ah[1][0],ah[1][1],ah[1][2],ah[1][3], aAh + aoff + 16*24*2);
        LDSM4(al[0][0],al[0][1],al[0][2],al[0][3], aAl + aoff);
        LDSM4(al[1][0],al[1][1],al[1][2],al[1][3], aAl + aoff + 16*24*2);
        LDSM4T(bh[0][0],bh[0][1],bh[1][0],bh[1][1], aB0h + boff);
        LDSM4T(bh[2][0],bh[2][1],bh[3][0],bh[3][1], aB0h + boff + 16*2);
        LDSM4T(bl[0][0],bl[0][1],bl[1][0],bl[1][1], aB0l + boff);
        LDSM4T(bl[2][0],bl[2][1],bl[3][0],bl[3][1], aB0l + boff + 16*2);
        #pragma unroll
        for (int mt=0;mt<2;mt++)
            #pragma unroll
            for (int nt=0;nt<4;nt++){
                MMA_BF16(acc[mt][nt], ah[mt], bh[nt][0], bh[nt][1]);
                MMA_BF16(acc[mt][nt], ah[mt], bl[nt][0], bl[nt][1]);
                MMA_BF16(acc[mt][nt], al[mt], bh[nt][0], bh[nt][1]);
            }
        if (more){
            int nb = buf^1;
            float av[8]={pa0.x,pa0.y,pa0.z,pa0.w,pa1.x,pa1.y,pa1.z,pa1.w};
            unsigned short hh[8], ll[8];
            #pragma unroll
            for (int j=0;j<8;j++) bfsplit(av[j], hh[j], ll[j]);
            *(uint4*)&Ah[nb][ar][akq] = *(uint4*)hh;
            *(uint4*)&Al[nb][ar][akq] = *(uint4*)ll;
            float bv[4]={pb0.x,pb0.y,pb0.z,pb0.w};
            unsigned short bh4[4], bl4[4];
            #pragma unroll
            for (int j=0;j<4;j++) bfsplit(bv[j], bh4[j], bl4[j]);
            *(uint2*)&Bh[nb][bkr][bnq] = *(uint2*)bh4;
            *(uint2*)&Bl[nb][bkr][bnq] = *(uint2*)bl4;
        }
        __syncthreads();
        buf ^= 1;
    }

    #pragma unroll
    for (int mt=0;mt<2;mt++){
        int row = m0 + wm*32 + mt*16 + g;
        float bv0 = bias[row], bv1 = bias[row+8];
        #pragma unroll
        for (int nt=0;nt<4;nt++){
            size_t o0 = (size_t)row*PIX + pix0 + wn*32 + nt*8 + 2*tq;
            size_t o1 = o0 + (size_t)8*PIX;
            if (mode==0){
                float2 v0 = make_float2(gelu_tanh(acc[mt][nt][0]+bv0), gelu_tanh(acc[mt][nt][1]+bv0));
                float2 v1 = make_float2(gelu_tanh(acc[mt][nt][2]+bv1), gelu_tanh(acc[mt][nt][3]+bv1));
                *(float2*)(Cg+o0) = v0;
                *(float2*)(Cg+o1) = v1;
            } else {
                float2 h0 = *(const float2*)(Cg+o0);
                float2 h1 = *(const float2*)(Cg+o1);
                *(float2*)(Cg+o0) = make_float2(acc[mt][nt][0]+bv0+h0.x, acc[mt][nt][1]+bv0+h0.y);
                *(float2*)(Cg+o1) = make_float2(acc[mt][nt][2]+bv1+h1.x, acc[mt][nt][3]+bv1+h1.y);
            }
        }
    }
}

// ---------------- decoder ----------------
__global__ void k_decoder(const float* __restrict__ wdec, const float* __restrict__ bdec,
                          float* __restrict__ out){
    int b  = blockIdx.y;
    int p0 = blockIdx.x*256;
    int t  = threadIdx.x;
    __shared__ float ws[8][256];
    #pragma unroll
    for (int j=0;j<8;j++) ws[j][t] = wdec[j*CEMB + t];
    __syncthreads();
    float acc[8];
    #pragma unroll
    for (int o=0;o<8;o++) acc[o] = bdec[o];
    for (int c=0;c<CEMB;c++){
        float v = g_h[((size_t)b*CEMB + c)*PIX + p0 + t];
        #pragma unroll
        for (int o=0;o<8;o++) acc[o] = fmaf(v, ws[o][c], acc[o]);
    }
    #pragma unroll
    for (int o=0;o<8;o++)
        out[((size_t)b*8 + o)*PIX + p0 + t] = acc[o];
}

// ---------------- launch ----------------
extern "C" void kernel_launch(void* const* d_in, const int* in_sizes, int n_in,
                              void* d_out, int out_size){
    const float* x      = (const float*)d_in[0];
    const float* w_enc  = (const float*)d_in[1];
    const float* b_enc  = (const float*)d_in[2];
    const float* pos    = (const float*)d_in[3];
    const float* spec_w = (const float*)d_in[4];
    const float* w1     = (const float*)d_in[5];
    const float* b1     = (const float*)d_in[6];
    const float* w2     = (const float*)d_in[7];
    const float* b2     = (const float*)d_in[8];
    const float* w_dec  = (const float*)d_in[9];
    const float* b_dec  = (const float*)d_in[10];
    const float* sht_wt = (const float*)d_in[11];
    const float* isht_wt= (const float*)d_in[12];
    float* out = (float*)d_out;

    cudaFuncSetAttribute(k_dhconv_mma, cudaFuncAttributeMaxDynamicSharedMemorySize, DSM_TOTAL);
    cudaFuncSetAttribute(k_legfwd_mma, cudaFuncAttributeMaxDynamicSharedMemorySize, LF_TOTAL);

    ushort_t *wth, *wtl, *iwh, *iwl;
    cudaGetSymbolAddress((void**)&wth, g_wth); cudaGetSymbolAddress((void**)&wtl, g_wtl);
    cudaGetSymbolAddress((void**)&iwh, g_iwh); cudaGetSymbolAddress((void**)&iwl, g_iwl);

    k_dftinit<<<NP,256>>>();
    k_wsplit<<<MM*LL, 128>>>(sht_wt, wth, wtl);
    k_wsplit<<<MM*LL, 128>>>(isht_wt, iwh, iwl);
    k_wtrans<<<dim3(32, CEMB, NLAYER), dim3(32,8)>>>(spec_w);
    k_encoder<<<dim3(PIX/256, BB, 4), 256>>>(x, w_enc, b_enc, pos);

    for (int layer=0; layer<NLAYER; layer++){
        k_fftfwd_mma<<<dim3(BCK/128, 4), 256>>>();
        k_fft_m128<<<BCK/8, 256>>>();
        k_legfwd_mma<<<dim3(BC/128, LL/64, MM), 256, LF_TOTAL>>>();
        k_dhconv_mma<<<dim3(2, 4, LL), 256, DSM_TOTAL>>>(layer);
        k_dhconv_tail<<<LL, 256>>>(layer);
        k_legbwd_mma<<<dim3(BC/128, KLAT/64, MM), 256>>>();
        k_fftinv_mma<<<dim3(BCK/128, NLON/64), 256>>>();
        k_mlp_mma<<<dim3(PIX/64, HID/128, BB), 256>>>(0, CEMB, w1 + (size_t)layer*HID*CEMB, b1 + layer*HID);
        k_mlp_mma<<<dim3(PIX/64, CEMB/128, BB), 256>>>(1, HID,  w2 + (size_t)layer*CEMB*HID, b2 + layer*CEMB);
    }

    k_decoder<<<dim3(PIX/256, BB), 256>>>(w_dec, b_dec, out);
}

// round 16
// speedup vs baseline: 1.0719x; 1.0719x over previous
#include <cuda_runtime.h>
#include <cuda_bf16.h>
#include <math.h>
#include <stdint.h>

#define BB     2
#define CEMB   256
#define KLAT   128
#define NLON   256
#define MM     129
#define MMP    136
#define LL     128
#define HID    512
#define NLAYER 4
#define PIX    (KLAT*NLON)
#define BC     (BB*CEMB)
#define ROWS2  (BB*MM)
#define RC     (ROWS2*CEMB)
#define BCK    (BC*KLAT)
#define NP     320
#define KINV   272

typedef unsigned long long ull;
typedef unsigned short ushort_t;

// ---------------- scratch ----------------
__device__ float g_h [BB*CEMB*PIX];
__device__ float g_t [BB*HID*PIX];
__device__ float g_Fr[MM*BCK];
__device__ float g_Fi[MM*BCK];
__device__ float g_Dr[LL*RC];
__device__ float g_Di[LL*RC];
__device__ float g_Er[LL*RC];
__device__ float g_Ei[LL*RC];
__device__ float g_Yr[(size_t)MMP*BCK];
__device__ float g_Yi[(size_t)MMP*BCK];
// spec_w bf16 hi/lo planes  [layer][l][i][o]
__device__ ushort_t g_Brh[(size_t)NLAYER*LL*CEMB*CEMB];
__device__ ushort_t g_Brl[(size_t)NLAYER*LL*CEMB*CEMB];
__device__ ushort_t g_Bih[(size_t)NLAYER*LL*CEMB*CEMB];
__device__ ushort_t g_Bil[(size_t)NLAYER*LL*CEMB*CEMB];
// static bf16 hi/lo planes
__device__ ushort_t g_dfh[NLON*NP], g_dfl[NLON*NP];
__device__ ushort_t g_dih[KINV*NLON], g_dil[KINV*NLON];
__device__ ushort_t g_wth[MM*LL*KLAT], g_wtl[MM*LL*KLAT];
__device__ ushort_t g_iwh[MM*LL*KLAT], g_iwl[MM*LL*KLAT];

__device__ __forceinline__ float gelu_tanh(float x){
    float x3 = x*x*x;
    float z = 0.7978845608028654f*fmaf(0.044715f, x3, x);
    float t;
    asm("tanh.approx.f32 %0, %1;" : "=f"(t) : "f"(z));
    return 0.5f*x*(1.f + t);
}
__device__ __forceinline__ void bfsplit(float v, unsigned short &h, unsigned short &l){
    __nv_bfloat16 hb = __float2bfloat16(v);
    float r = v - __bfloat162float(hb);
    h = __bfloat16_as_ushort(hb);
    l = __bfloat16_as_ushort(__float2bfloat16(r));
}
__device__ __forceinline__ float bf2f(unsigned short u){
    return __bfloat162float(__ushort_as_bfloat16(u));
}
__device__ __forceinline__ uint32_t smem_u32(const void* p){
    uint32_t a;
    asm("{ .reg .u64 t; cvta.to.shared.u64 t, %1; cvt.u32.u64 %0, t; }" : "=r"(a) : "l"(p));
    return a;
}
#define LDSM4(r0,r1,r2,r3,addr) \
    asm volatile("ldmatrix.sync.aligned.m8n8.x4.shared.b16 {%0,%1,%2,%3}, [%4];" \
        : "=r"(r0),"=r"(r1),"=r"(r2),"=r"(r3) : "r"(addr))
#define LDSM4T(r0,r1,r2,r3,addr) \
    asm volatile("ldmatrix.sync.aligned.m8n8.x4.trans.shared.b16 {%0,%1,%2,%3}, [%4];" \
        : "=r"(r0),"=r"(r1),"=r"(r2),"=r"(r3) : "r"(addr))
#define MMA_BF16(d, a, b0, b1) \
    asm volatile("mma.sync.aligned.m16n8k16.row.col.f32.bf16.bf16.f32 " \
        "{%0,%1,%2,%3}, {%4,%5,%6,%7}, {%8,%9}, {%0,%1,%2,%3};" \
        : "+f"(d[0]),"+f"(d[1]),"+f"(d[2]),"+f"(d[3]) \
        : "r"(a[0]),"r"(a[1]),"r"(a[2]),"r"(a[3]), "r"(b0),"r"(b1))

// ---------------- init ----------------
__global__ void k_dftinit(){
    int c = blockIdx.x;
    int n = threadIdx.x;
    float fwdv = 0.f, invv = 0.f;
    if (c < 2*MM){
        int m = c >> 1;
        int ph = (m*n) & 255;
        double a = 6.283185307179586476925286766559 * (double)ph / 256.0;
        double base = (c & 1) ? -sin(a) : cos(a);
        fwdv = (float)(base * (6.283185307179586476925286766559/256.0));
        double s = (m==0 || m==MM-1) ? 1.0 : 2.0;
        invv = (float)(base * s);
    }
    unsigned short fh, fl;
    bfsplit(fwdv, fh, fl);
    g_dfh[(size_t)n*NP + c] = fh;
    g_dfl[(size_t)n*NP + c] = fl;
    if (c < KINV){
        unsigned short ih, il;
        bfsplit(invv, ih, il);
        g_dih[(size_t)c*NLON + n] = ih;
        g_dil[(size_t)c*NLON + n] = il;
    }
}

__global__ void k_wsplit(const float* __restrict__ wt, ushort_t* __restrict__ h,
                         ushort_t* __restrict__ l){
    size_t i = (size_t)blockIdx.x*128 + threadIdx.x;
    float v = wt[i];
    unsigned short hh, ll;
    bfsplit(v, hh, ll);
    h[i] = hh;
    l[i] = ll;
}

// spec_w [L][i][o][l][2] -> bf16 planes [layer][l][i][o]; packed uint32 stores
__global__ void k_wtrans(const float* __restrict__ sw){
    __shared__ float2 tile[32][33];
    const int lt = blockIdx.x & 3;
    const int ot = blockIdx.x >> 2;
    const int i  = blockIdx.y;
    const int ly = blockIdx.z;
    const int l0 = lt*32, o0 = ot*32;
    const int x = threadIdx.x, y = threadIdx.y;
    for (int r=y; r<32; r+=8){
        size_t src = (((size_t)(ly*CEMB + i))*CEMB + (o0+r))*LL + l0 + x;
        tile[r][x] = *(const float2*)(sw + src*2);
    }
    __syncthreads();
    const int xx = x & 15, xh = x >> 4;
    #pragma unroll
    for (int j=0;j<2;j++){
        int r = y*2 + xh + 16*j;
        float2 wa = tile[2*xx][r];
        float2 wb = tile[2*xx+1][r];
        unsigned short rha,rla,iha,ila, rhb,rlb,ihb,ilb;
        bfsplit(wa.x, rha, rla); bfsplit(wa.y, iha, ila);
        bfsplit(wb.x, rhb, rlb); bfsplit(wb.y, ihb, ilb);
        size_t dst = (((size_t)(ly*LL + l0 + r))*CEMB + i)*CEMB + o0 + 2*xx;
        *(uint32_t*)&g_Brh[dst] = (uint32_t)rha | ((uint32_t)rhb<<16);
        *(uint32_t*)&g_Brl[dst] = (uint32_t)rla | ((uint32_t)rlb<<16);
        *(uint32_t*)&g_Bih[dst] = (uint32_t)iha | ((uint32_t)ihb<<16);
        *(uint32_t*)&g_Bil[dst] = (uint32_t)ila | ((uint32_t)ilb<<16);
    }
}

// encoder: o-dim split over blockIdx.z
__global__ void k_encoder(const float* __restrict__ x, const float* __restrict__ wenc,
                          const float* __restrict__ benc, const float* __restrict__ pos){
    int b  = blockIdx.y;
    int p0 = blockIdx.x*256;
    int oc = blockIdx.z*64;
    int t  = threadIdx.x;
    __shared__ float ws[64][8];
    if (t < 64){
        #pragma unroll
        for (int j=0;j<8;j++) ws[t][j] = wenc[(oc+t)*8+j];
    }
    __syncthreads();
    float xv[8];
    #pragma unroll
    for (int c=0;c<8;c++) xv[c] = x[((size_t)b*8 + c)*PIX + p0 + t];
    for (int oo=0;oo<64;oo++){
        int o = oc + oo;
        float acc = benc[o];
        #pragma unroll
        for (int c=0;c<8;c++) acc = fmaf(xv[c], ws[oo][c], acc);
        g_h[((size_t)b*CEMB + o)*PIX + p0 + t] = acc + pos[(size_t)o*PIX + p0 + t];
    }
}

// ---- fft forward via warp MMA (proven)
__global__ void __launch_bounds__(256) k_fftfwd_mma(){
    __shared__ __align__(16) __nv_bfloat16 Ah[2][128][24], Al[2][128][24];
    __shared__ __align__(16) __nv_bfloat16 Bh[2][16][72],  Bl[2][16][72];
    const int bm0 = blockIdx.x*128;
    const int c0  = blockIdx.y*64;
    const int tid=threadIdx.x, wid=tid>>5, lane=tid&31;
    const int wm=wid>>1, wn=wid&1;
    const int g=lane>>2, tq=lane&3;
    const int ar=tid>>1, akq=(tid&1)*8;
    const int bkr=tid>>4, bnq=(tid&15)*4;
    const int lar=(lane&15), lac=(lane>>4)*8;
    uint32_t aAh = smem_u32(&Ah[0][wm*32 + lar][lac]);
    uint32_t aAl = smem_u32(&Al[0][wm*32 + lar][lac]);
    uint32_t aBh = smem_u32(&Bh[0][lar][wn*32 + lac]);
    uint32_t aBl = smem_u32(&Bl[0][lar][wn*32 + lac]);
    const uint32_t ABUF = 2*128*24, BBUF = 2*16*72;

    float acc[2][4][4];
    #pragma unroll
    for (int i=0;i<2;i++)
        #pragma unroll
        for (int j=0;j<4;j++)
            #pragma unroll
            for (int q=0;q<4;q++) acc[i][j][q]=0.f;

    {
        float4 a0 = *(const float4*)(g_h + (size_t)(bm0+ar)*NLON + akq);
        float4 a1 = *(const float4*)(g_h + (size_t)(bm0+ar)*NLON + akq + 4);
        float av[8]={a0.x,a0.y,a0.z,a0.w,a1.x,a1.y,a1.z,a1.w};
        unsigned short hh[8], ll[8];
        #pragma unroll
        for (int j=0;j<8;j++) bfsplit(av[j], hh[j], ll[j]);
        *(uint4*)&Ah[0][ar][akq] = *(uint4*)hh;
        *(uint4*)&Al[0][ar][akq] = *(uint4*)ll;
        *(uint2*)&Bh[0][bkr][bnq] = *(const uint2*)&g_dfh[(size_t)bkr*NP + c0 + bnq];
        *(uint2*)&Bl[0][bkr][bnq] = *(const uint2*)&g_dfl[(size_t)bkr*NP + c0 + bnq];
    }
    __syncthreads();

    int buf=0;
    for (int s=0;s<16;s++){
        float4 pa0, pa1; uint2 pbh, pbl;
        bool more = (s+1<16);
        if (more){
            int k0=(s+1)*16;
            pa0 = *(const float4*)(g_h + (size_t)(bm0+ar)*NLON + k0 + akq);
            pa1 = *(const float4*)(g_h + (size_t)(bm0+ar)*NLON + k0 + akq + 4);
            pbh = *(const uint2*)&g_dfh[(size_t)(k0+bkr)*NP + c0 + bnq];
            pbl = *(const uint2*)&g_dfl[(size_t)(k0+bkr)*NP + c0 + bnq];
        }
        uint32_t ah[2][4], al[2][4], bh[4][2], bl[4][2];
        uint32_t aoff = buf*ABUF, boff = buf*BBUF;
        LDSM4(ah[0][0],ah[0][1],ah[0][2],ah[0][3], aAh + aoff);
        LDSM4(ah[1][0],ah[1][1],ah[1][2],ah[1][3], aAh + aoff + 16*24*2);
        LDSM4(al[0][0],al[0][1],al[0][2],al[0][3], aAl + aoff);
        LDSM4(al[1][0],al[1][1],al[1][2],al[1][3], aAl + aoff + 16*24*2);
        LDSM4T(bh[0][0],bh[0][1],bh[1][0],bh[1][1], aBh + boff);
        LDSM4T(bh[2][0],bh[2][1],bh[3][0],bh[3][1], aBh + boff + 16*2);
        LDSM4T(bl[0][0],bl[0][1],bl[1][0],bl[1][1], aBl + boff);
        LDSM4T(bl[2][0],bl[2][1],bl[3][0],bl[3][1], aBl + boff + 16*2);
        #pragma unroll
        for (int mt=0;mt<2;mt++)
            #pragma unroll
            for (int nt=0;nt<4;nt++){
                MMA_BF16(acc[mt][nt], ah[mt], bh[nt][0], bh[nt][1]);
                MMA_BF16(acc[mt][nt], ah[mt], bl[nt][0], bl[nt][1]);
                MMA_BF16(acc[mt][nt], al[mt], bh[nt][0], bh[nt][1]);
            }
        if (more){
            int nb = buf^1;
            float av[8]={pa0.x,pa0.y,pa0.z,pa0.w,pa1.x,pa1.y,pa1.z,pa1.w};
            unsigned short hh[8], ll[8];
            #pragma unroll
            for (int j=0;j<8;j++) bfsplit(av[j], hh[j], ll[j]);
            *(uint4*)&Ah[nb][ar][akq] = *(uint4*)hh;
            *(uint4*)&Al[nb][ar][akq] = *(uint4*)ll;
            *(uint2*)&Bh[nb][bkr][bnq] = pbh;
            *(uint2*)&Bl[nb][bkr][bnq] = pbl;
        }
        __syncthreads();
        buf ^= 1;
    }

    #pragma unroll
    for (int mt=0;mt<2;mt++){
        int row = bm0 + wm*32 + mt*16 + g;
        #pragma unroll
        for (int nt=0;nt<4;nt++){
            int m = (c0 + wn*32 + nt*8 + 2*tq) >> 1;
            size_t o = (size_t)m*BCK + row;
            g_Fr[o]   = acc[mt][nt][0];
            g_Fi[o]   = acc[mt][nt][1];
            g_Fr[o+8] = acc[mt][nt][2];
            g_Fi[o+8] = acc[mt][nt][3];
        }
    }
}

// ---- m=128 bin
__global__ void k_fft_m128(){
    int row  = blockIdx.x*8 + (threadIdx.x>>5);
    int lane = threadIdx.x&31;
    const float4* p = (const float4*)(g_h + (size_t)row*NLON);
    float4 x0 = p[lane], x1 = p[lane+32];
    float s = x0.x-x0.y+x0.z-x0.w + x1.x-x1.y+x1.z-x1.w;
    #pragma unroll
    for (int o=16;o;o>>=1) s += __shfl_xor_sync(0xFFFFFFFFu, s, o);
    if (lane==0) g_Fr[(size_t)128*BCK + row] = s * (6.283185307179586f/256.f);
}

// ---- Legendre fwd via warp MMA (proven)
#define LFA 3072
#define LFB 1536
#define LF_FRH 0
#define LF_FRL (2*LFA)
#define LF_FIH (4*LFA)
#define LF_FIL (6*LFA)
#define LF_WH  (8*LFA)
#define LF_WL  (8*LFA + 2*LFB)
#define LF_TOTAL ((8*LFA + 4*LFB)*2)

__global__ void __launch_bounds__(256) k_legfwd_mma(){
    extern __shared__ __nv_bfloat16 lsm[];
    const int m   = blockIdx.z;
    const int bm0 = blockIdx.x*128;
    const int l0  = blockIdx.y*64;
    const float* __restrict__ Ar = g_Fr + (size_t)m*BCK;
    const float* __restrict__ Ai = g_Fi + (size_t)m*BCK;
    const ushort_t* __restrict__ Wh = g_wth + (size_t)m*LL*KLAT;
    const ushort_t* __restrict__ Wl = g_wtl + (size_t)m*LL*KLAT;

    const int tid=threadIdx.x, wid=tid>>5, lane=tid&31;
    const int wm=wid>>1, wn=wid&1;
    const int g=lane>>2, tq=lane&3;
    const int ar=tid>>1, akq=(tid&1)*8;
    const int br=tid>>2, bkq=(tid&3)*4;
    const int lar=(lane&15), lac=(lane>>4)*8;
    const int sel=lane>>3, rowg=lane&7;
    const int bn_add=(sel>>1)*8, bk_add=(sel&1)*8;

    const uint32_t sb = smem_u32(lsm);
    uint32_t aFRH = sb + (LF_FRH + (wm*32+lar)*24 + lac)*2;
    uint32_t aFRL = sb + (LF_FRL + (wm*32+lar)*24 + lac)*2;
    uint32_t aFIH = sb + (LF_FIH + (wm*32+lar)*24 + lac)*2;
    uint32_t aFIL = sb + (LF_FIL + (wm*32+lar)*24 + lac)*2;
    uint32_t aWH0 = sb + (LF_WH + (wn*32 + bn_add + rowg)*24 + bk_add)*2;
    uint32_t aWL0 = sb + (LF_WL + (wn*32 + bn_add + rowg)*24 + bk_add)*2;

    float accR[2][4][4], accI[2][4][4];
    #pragma unroll
    for (int i=0;i<2;i++)
        #pragma unroll
        for (int j=0;j<4;j++)
            #pragma unroll
            for (int q=0;q<4;q++){ accR[i][j][q]=0.f; accI[i][j][q]=0.f; }

    {
        float4 r0 = *(const float4*)(Ar + (size_t)(bm0+ar)*KLAT + akq);
        float4 r1 = *(const float4*)(Ar + (size_t)(bm0+ar)*KLAT + akq + 4);
        float4 i0 = *(const float4*)(Ai + (size_t)(bm0+ar)*KLAT + akq);
        float4 i1 = *(const float4*)(Ai + (size_t)(bm0+ar)*KLAT + akq + 4);
        float rv[8]={r0.x,r0.y,r0.z,r0.w,r1.x,r1.y,r1.z,r1.w};
        float iv[8]={i0.x,i0.y,i0.z,i0.w,i1.x,i1.y,i1.z,i1.w};
        unsigned short rh[8], rl[8], ih[8], il[8];
        #pragma unroll
        for (int j=0;j<8;j++){ bfsplit(rv[j], rh[j], rl[j]); bfsplit(iv[j], ih[j], il[j]); }
        int ao = ar*24 + akq;
        *(uint4*)&lsm[LF_FRH+ao] = *(uint4*)rh;
        *(uint4*)&lsm[LF_FRL+ao] = *(uint4*)rl;
        *(uint4*)&lsm[LF_FIH+ao] = *(uint4*)ih;
        *(uint4*)&lsm[LF_FIL+ao] = *(uint4*)il;
        int bo = br*24 + bkq;
        *(uint2*)&lsm[LF_WH+bo] = *(const uint2*)&Wh[(size_t)(l0+br)*KLAT + bkq];
        *(uint2*)&lsm[LF_WL+bo] = *(const uint2*)&Wl[(size_t)(l0+br)*KLAT + bkq];
    }
    __syncthreads();

    int buf=0;
    for (int s=0;s<8;s++){
        float4 pr0, pr1, pi0, pi1; uint2 pwh, pwl;
        bool more = (s+1<8);
        if (more){
            int k0=(s+1)*16;
            pr0 = *(const float4*)(Ar + (size_t)(bm0+ar)*KLAT + k0 + akq);
            pr1 = *(const float4*)(Ar + (size_t)(bm0+ar)*KLAT + k0 + akq + 4);
            pi0 = *(const float4*)(Ai + (size_t)(bm0+ar)*KLAT + k0 + akq);
            pi1 = *(const float4*)(Ai + (size_t)(bm0+ar)*KLAT + k0 + akq + 4);
            pwh = *(const uint2*)&Wh[(size_t)(l0+br)*KLAT + k0 + bkq];
            pwl = *(const uint2*)&Wl[(size_t)(l0+br)*KLAT + k0 + bkq];
        }
        const uint32_t aof = buf*LFA*2;
        const uint32_t bof = buf*LFB*2;
        uint32_t frh[2][4], frl[2][4], fih[2][4], fil[2][4];
        LDSM4(frh[0][0],frh[0][1],frh[0][2],frh[0][3], aFRH+aof);
        LDSM4(frh[1][0],frh[1][1],frh[1][2],frh[1][3], aFRH+aof+16*24*2);
        LDSM4(frl[0][0],frl[0][1],frl[0][2],frl[0][3], aFRL+aof);
        LDSM4(frl[1][0],frl[1][1],frl[1][2],frl[1][3], aFRL+aof+16*24*2);
        LDSM4(fih[0][0],fih[0][1],fih[0][2],fih[0][3], aFIH+aof);
        LDSM4(fih[1][0],fih[1][1],fih[1][2],fih[1][3], aFIH+aof+16*24*2);
        LDSM4(fil[0][0],fil[0][1],fil[0][2],fil[0][3], aFIL+aof);
        LDSM4(fil[1][0],fil[1][1],fil[1][2],fil[1][3], aFIL+aof+16*24*2);
        uint32_t wh[4][2], wl[4][2];
        LDSM4(wh[0][0],wh[0][1],wh[1][0],wh[1][1], aWH0+bof);
        LDSM4(wh[2][0],wh[2][1],wh[3][0],wh[3][1], aWH0+bof+16*24*2);
        LDSM4(wl[0][0],wl[0][1],wl[1][0],wl[1][1], aWL0+bof);
        LDSM4(wl[2][0],wl[2][1],wl[3][0],wl[3][1], aWL0+bof+16*24*2);
        #pragma unroll
        for (int mt=0;mt<2;mt++)
            #pragma unroll
            for (int nt=0;nt<4;nt++){
                MMA_BF16(accR[mt][nt], frh[mt], wh[nt][0], wh[nt][1]);
                MMA_BF16(accR[mt][nt], frh[mt], wl[nt][0], wl[nt][1]);
                MMA_BF16(accR[mt][nt], frl[mt], wh[nt][0], wh[nt][1]);
                MMA_BF16(accI[mt][nt], fih[mt], wh[nt][0], wh[nt][1]);
                MMA_BF16(accI[mt][nt], fih[mt], wl[nt][0], wl[nt][1]);
                MMA_BF16(accI[mt][nt], fil[mt], wh[nt][0], wh[nt][1]);
            }
        if (more){
            int nb = buf^1;
            float rv[8]={pr0.x,pr0.y,pr0.z,pr0.w,pr1.x,pr1.y,pr1.z,pr1.w};
            float iv[8]={pi0.x,pi0.y,pi0.z,pi0.w,pi1.x,pi1.y,pi1.z,pi1.w};
            unsigned short rh[8], rl[8], ih[8], il[8];
            #pragma unroll
            for (int j=0;j<8;j++){ bfsplit(rv[j], rh[j], rl[j]); bfsplit(iv[j], ih[j], il[j]); }
            int ao = nb*LFA + ar*24 + akq;
            *(uint4*)&lsm[LF_FRH+ao] = *(uint4*)rh;
            *(uint4*)&lsm[LF_FRL+ao] = *(uint4*)rl;
            *(uint4*)&lsm[LF_FIH+ao] = *(uint4*)ih;
            *(uint4*)&lsm[LF_FIL+ao] = *(uint4*)il;
            int bo = nb*LFB + br*24 + bkq;
            *(uint2*)&lsm[LF_WH+bo] = pwh;
            *(uint2*)&lsm[LF_WL+bo] = pwl;
        }
        __syncthreads();
        buf ^= 1;
    }

    #pragma unroll
    for (int mt=0;mt<2;mt++){
        int row = bm0 + wm*32 + mt*16 + g;
        #pragma unroll
        for (int nt=0;nt<4;nt++){
            int lcol = l0 + wn*32 + nt*8 + 2*tq;
            #pragma unroll
            for (int q=0;q<2;q++){
                int l = lcol + q;
                int r0 = row, r1 = row+8;
                size_t o0 = (((size_t)l*BB + (r0>>8))*MM + m)*CEMB + (r0&255);
                size_t o1 = (((size_t)l*BB + (r1>>8))*MM + m)*CEMB + (r1&255);
                g_Dr[o0] = accR[mt][nt][q];
                g_Di[o0] = accI[mt][nt][q];
                g_Dr[o1] = accR[mt][nt][2+q];
                g_Di[o1] = accI[mt][nt][2+q];
            }
        }
    }
}

// ---- dhconv via warp MMA: bx<2 = MMA rows 0..255 (no guards); bx==2,by==0 = tail rows 256-257
#define DA_BUF 3072
#define DB_BUF 1152
#define DOF_DRH 0
#define DOF_DRL (2*DA_BUF)
#define DOF_DIH (4*DA_BUF)
#define DOF_DIL (6*DA_BUF)
#define DOF_BRH (8*DA_BUF)
#define DOF_BRL (8*DA_BUF + 2*DB_BUF)
#define DOF_BIH (8*DA_BUF + 4*DB_BUF)
#define DOF_BIL (8*DA_BUF + 6*DB_BUF)
#define DOF_BNH (8*DA_BUF + 8*DB_BUF)
#define DOF_BNL (8*DA_BUF + 10*DB_BUF)
#define DSM_TOTAL ((8*DA_BUF + 12*DB_BUF)*2)

__global__ void __launch_bounds__(256) k_dhconv_mma(int layer){
    extern __shared__ __nv_bfloat16 dsm[];
    const int l   = blockIdx.z;
    const size_t wbase = ((size_t)(layer*LL + l))*CEMB*CEMB;
    const int tid = threadIdx.x;

    if (blockIdx.x == 2){
        // ---- fused tail: rows 256,257 for this l (only by==0 works) ----
        if (blockIdx.y != 0) return;
        __shared__ float dr[2][CEMB], di[2][CEMB];
        const int o = tid;
        const size_t abase = (size_t)l*RC + (size_t)256*CEMB;
        dr[0][o] = g_Dr[abase + o];
        di[0][o] = g_Di[abase + o];
        dr[1][o] = g_Dr[abase + CEMB + o];
        di[1][o] = g_Di[abase + CEMB + o];
        __syncthreads();
        float er0=0.f, ei0=0.f, er1=0.f, ei1=0.f;
        #pragma unroll 4
        for (int i=0;i<CEMB;i++){
            size_t wb = wbase + (size_t)i*CEMB + o;
            float wr = bf2f(__ldg(&g_Brh[wb])) + bf2f(__ldg(&g_Brl[wb]));
            float wi = bf2f(__ldg(&g_Bih[wb])) + bf2f(__ldg(&g_Bil[wb]));
            float r0=dr[0][i], i0=di[0][i], r1=dr[1][i], i1=di[1][i];
            er0 = fmaf(r0, wr, er0); er0 = fmaf(-i0, wi, er0);
            ei0 = fmaf(r0, wi, ei0); ei0 = fmaf( i0, wr, ei0);
            er1 = fmaf(r1, wr, er1); er1 = fmaf(-i1, wi, er1);
            ei1 = fmaf(r1, wi, ei1); ei1 = fmaf( i1, wr, ei1);
        }
        g_Er[abase + o] = er0;        g_Ei[abase + o] = ei0;
        g_Er[abase + CEMB + o] = er1; g_Ei[abase + CEMB + o] = ei1;
        return;
    }

    const int bm0 = blockIdx.x*128;
    const int o0  = blockIdx.y*64;
    const float* __restrict__ Ar = g_Dr + (size_t)l*RC;
    const float* __restrict__ Ai = g_Di + (size_t)l*RC;

    const int wid=tid>>5, lane=tid&31;
    const int wm=wid>>1, wn=wid&1;
    const int g=lane>>2, tq=lane&3;
    const int ar=tid>>1, akq=(tid&1)*8;
    const int bkr=tid>>4, bnq=(tid&15)*4;
    const int lar=(lane&15), lac=(lane>>4)*8;

    const uint32_t sb = smem_u32(dsm);
    uint32_t aDRH = sb + (DOF_DRH + (wm*32+lar)*24 + lac)*2;
    uint32_t aDRL = sb + (DOF_DRL + (wm*32+lar)*24 + lac)*2;
    uint32_t aDIH = sb + (DOF_DIH + (wm*32+lar)*24 + lac)*2;
    uint32_t aDIL = sb + (DOF_DIL + (wm*32+lar)*24 + lac)*2;
    uint32_t aBRH = sb + (DOF_BRH + lar*72 + wn*32 + lac)*2;
    uint32_t aBRL = sb + (DOF_BRL + lar*72 + wn*32 + lac)*2;
    uint32_t aBIH = sb + (DOF_BIH + lar*72 + wn*32 + lac)*2;
    uint32_t aBIL = sb + (DOF_BIL + lar*72 + wn*32 + lac)*2;
    uint32_t aBNH = sb + (DOF_BNH + lar*72 + wn*32 + lac)*2;
    uint32_t aBNL = sb + (DOF_BNL + lar*72 + wn*32 + lac)*2;

    float accR[2][4][4], accI[2][4][4];
    #pragma unroll
    for (int i=0;i<2;i++)
        #pragma unroll
        for (int j=0;j<4;j++)
            #pragma unroll
            for (int q=0;q<4;q++){ accR[i][j][q]=0.f; accI[i][j][q]=0.f; }

    const int arow = bm0 + ar;

    {
        float4 r0 = *(const float4*)(Ar + (size_t)arow*CEMB + akq);
        float4 r1 = *(const float4*)(Ar + (size_t)arow*CEMB + akq + 4);
        float4 i0 = *(const float4*)(Ai + (size_t)arow*CEMB + akq);
        float4 i1 = *(const float4*)(Ai + (size_t)arow*CEMB + akq + 4);
        float rv[8]={r0.x,r0.y,r0.z,r0.w,r1.x,r1.y,r1.z,r1.w};
        float iv[8]={i0.x,i0.y,i0.z,i0.w,i1.x,i1.y,i1.z,i1.w};
        unsigned short rh[8], rl[8], ih[8], il[8];
        #pragma unroll
        for (int j=0;j<8;j++){ bfsplit(rv[j], rh[j], rl[j]); bfsplit(iv[j], ih[j], il[j]); }
        int ao = ar*24 + akq;
        *(uint4*)&dsm[DOF_DRH+ao] = *(uint4*)rh;
        *(uint4*)&dsm[DOF_DRL+ao] = *(uint4*)rl;
        *(uint4*)&dsm[DOF_DIH+ao] = *(uint4*)ih;
        *(uint4*)&dsm[DOF_DIL+ao] = *(uint4*)il;
        size_t wb = wbase + (size_t)bkr*CEMB + o0 + bnq;
        uint2 wrh2 = *(const uint2*)&g_Brh[wb];
        uint2 wrl2 = *(const uint2*)&g_Brl[wb];
        uint2 wih2 = *(const uint2*)&g_Bih[wb];
        uint2 wil2 = *(const uint2*)&g_Bil[wb];
        uint2 wnh2 = make_uint2(wih2.x^0x80008000u, wih2.y^0x80008000u);
        uint2 wnl2 = make_uint2(wil2.x^0x80008000u, wil2.y^0x80008000u);
        int bo = bkr*72 + bnq;
        *(uint2*)&dsm[DOF_BRH+bo] = wrh2;
        *(uint2*)&dsm[DOF_BRL+bo] = wrl2;
        *(uint2*)&dsm[DOF_BIH+bo] = wih2;
        *(uint2*)&dsm[DOF_BIL+bo] = wil2;
        *(uint2*)&dsm[DOF_BNH+bo] = wnh2;
        *(uint2*)&dsm[DOF_BNL+bo] = wnl2;
    }
    __syncthreads();

    int buf=0;
    for (int s=0;s<16;s++){
        float4 pr0, pr1, pi0, pi1;
        uint2 pwrh, pwrl, pwih, pwil;
        bool more = (s+1<16);
        if (more){
            int k0=(s+1)*16;
            pr0 = *(const float4*)(Ar + (size_t)arow*CEMB + k0 + akq);
            pr1 = *(const float4*)(Ar + (size_t)arow*CEMB + k0 + akq + 4);
            pi0 = *(const float4*)(Ai + (size_t)arow*CEMB + k0 + akq);
            pi1 = *(const float4*)(Ai + (size_t)arow*CEMB + k0 + akq + 4);
            size_t wb = wbase + (size_t)(k0+bkr)*CEMB + o0 + bnq;
            pwrh = *(const uint2*)&g_Brh[wb];
            pwrl = *(const uint2*)&g_Brl[wb];
            pwih = *(const uint2*)&g_Bih[wb];
            pwil = *(const uint2*)&g_Bil[wb];
        }
        const uint32_t aof = buf*DA_BUF*2;
        const uint32_t bof = buf*DB_BUF*2;
        uint32_t drh[2][4], drl[2][4], dih[2][4], dil[2][4];
        LDSM4(drh[0][0],drh[0][1],drh[0][2],drh[0][3], aDRH+aof);
        LDSM4(drh[1][0],drh[1][1],drh[1][2],drh[1][3], aDRH+aof+16*24*2);
        LDSM4(drl[0][0],drl[0][1],drl[0][2],drl[0][3], aDRL+aof);
        LDSM4(drl[1][0],drl[1][1],drl[1][2],drl[1][3], aDRL+aof+16*24*2);
        LDSM4(dih[0][0],dih[0][1],dih[0][2],dih[0][3], aDIH+aof);
        LDSM4(dih[1][0],dih[1][1],dih[1][2],dih[1][3], aDIH+aof+16*24*2);
        LDSM4(dil[0][0],dil[0][1],dil[0][2],dil[0][3], aDIL+aof);
        LDSM4(dil[1][0],dil[1][1],dil[1][2],dil[1][3], aDIL+aof+16*24*2);
        uint32_t brh[4][2], brl[4][2], bih[4][2], bil[4][2], bnh[4][2], bnl[4][2];
        LDSM4T(brh[0][0],brh[0][1],brh[1][0],brh[1][1], aBRH+bof);
        LDSM4T(brh[2][0],brh[2][1],brh[3][0],brh[3][1], aBRH+bof+16*2);
        LDSM4T(brl[0][0],brl[0][1],brl[1][0],brl[1][1], aBRL+bof);
        LDSM4T(brl[2][0],brl[2][1],brl[3][0],brl[3][1], aBRL+bof+16*2);
        LDSM4T(bih[0][0],bih[0][1],bih[1][0],bih[1][1], aBIH+bof);
        LDSM4T(bih[2][0],bih[2][1],bih[3][0],bih[3][1], aBIH+bof+16*2);
        LDSM4T(bil[0][0],bil[0][1],bil[1][0],bil[1][1], aBIL+bof);
        LDSM4T(bil[2][0],bil[2][1],bil[3][0],bil[3][1], aBIL+bof+16*2);
        LDSM4T(bnh[0][0],bnh[0][1],bnh[1][0],bnh[1][1], aBNH+bof);
        LDSM4T(bnh[2][0],bnh[2][1],bnh[3][0],bnh[3][1], aBNH+bof+16*2);
        LDSM4T(bnl[0][0],bnl[0][1],bnl[1][0],bnl[1][1], aBNL+bof);
        LDSM4T(bnl[2][0],bnl[2][1],bnl[3][0],bnl[3][1], aBNL+bof+16*2);
        #pragma unroll
        for (int mt=0;mt<2;mt++)
            #pragma unroll
            for (int nt=0;nt<4;nt++){
                MMA_BF16(accR[mt][nt], drh[mt], brh[nt][0], brh[nt][1]);
                MMA_BF16(accR[mt][nt], drh[mt], brl[nt][0], brl[nt][1]);
                MMA_BF16(accR[mt][nt], drl[mt], brh[nt][0], brh[nt][1]);
                MMA_BF16(accR[mt][nt], dih[mt], bnh[nt][0], bnh[nt][1]);
                MMA_BF16(accR[mt][nt], dih[mt], bnl[nt][0], bnl[nt][1]);
                MMA_BF16(accR[mt][nt], dil[mt], bnh[nt][0], bnh[nt][1]);
                MMA_BF16(accI[mt][nt], drh[mt], bih[nt][0], bih[nt][1]);
                MMA_BF16(accI[mt][nt], drh[mt], bil[nt][0], bil[nt][1]);
                MMA_BF16(accI[mt][nt], drl[mt], bih[nt][0], bih[nt][1]);
                MMA_BF16(accI[mt][nt], dih[mt], brh[nt][0], brh[nt][1]);
                MMA_BF16(accI[mt][nt], dih[mt], brl[nt][0], brl[nt][1]);
                MMA_BF16(accI[mt][nt], dil[mt], brh[nt][0], brh[nt][1]);
            }
        if (more){
            int nb = buf^1;
            float rv[8]={pr0.x,pr0.y,pr0.z,pr0.w,pr1.x,pr1.y,pr1.z,pr1.w};
            float iv[8]={pi0.x,pi0.y,pi0.z,pi0.w,pi1.x,pi1.y,pi1.z,pi1.w};
            unsigned short rh[8], rl[8], ih[8], il[8];
            #pragma unroll
            for (int j=0;j<8;j++){ bfsplit(rv[j], rh[j], rl[j]); bfsplit(iv[j], ih[j], il[j]); }
            int ao = nb*DA_BUF + ar*24 + akq;
            *(uint4*)&dsm[DOF_DRH+ao] = *(uint4*)rh;
            *(uint4*)&dsm[DOF_DRL+ao] = *(uint4*)rl;
            *(uint4*)&dsm[DOF_DIH+ao] = *(uint4*)ih;
            *(uint4*)&dsm[DOF_DIL+ao] = *(uint4*)il;
            uint2 wnh2 = make_uint2(pwih.x^0x80008000u, pwih.y^0x80008000u);
            uint2 wnl2 = make_uint2(pwil.x^0x80008000u, pwil.y^0x80008000u);
            int bo = nb*DB_BUF + bkr*72 + bnq;
            *(uint2*)&dsm[DOF_BRH+bo] = pwrh;
            *(uint2*)&dsm[DOF_BRL+bo] = pwrl;
            *(uint2*)&dsm[DOF_BIH+bo] = pwih;
            *(uint2*)&dsm[DOF_BIL+bo] = pwil;
            *(uint2*)&dsm[DOF_BNH+bo] = wnh2;
            *(uint2*)&dsm[DOF_BNL+bo] = wnl2;
        }
        __syncthreads();
        buf ^= 1;
    }

    #pragma unroll
    for (int mt=0;mt<2;mt++){
        int row = bm0 + wm*32 + mt*16 + g;
        #pragma unroll
        for (int nt=0;nt<4;nt++){
            int col = o0 + wn*32 + nt*8 + 2*tq;
            size_t o = (size_t)l*RC + (size_t)row*CEMB + col;
            *(float2*)(g_Er+o) = make_float2(accR[mt][nt][0], accR[mt][nt][1]);
            *(float2*)(g_Ei+o) = make_float2(accI[mt][nt][0], accI[mt][nt][1]);
            size_t o2 = o + (size_t)8*CEMB;
            *(float2*)(g_Er+o2) = make_float2(accR[mt][nt][2], accR[mt][nt][3]);
            *(float2*)(g_Ei+o2) = make_float2(accI[mt][nt][2], accI[mt][nt][3]);
        }
    }
}

// ---- Legendre bwd via warp MMA (proven)
#define LBA 2176
#define LBB 1152
#define LB_ERH 0
#define LB_ERL (2*LBA)
#define LB_EIH (4*LBA)
#define LB_EIL (6*LBA)
#define LB_WH  (8*LBA)
#define LB_WL  (8*LBA + 2*LBB)

__global__ void __launch_bounds__(256) k_legbwd_mma(){
    __shared__ __align__(16) __nv_bfloat16 lsm[8*LBA + 4*LBB];
    const int m   = blockIdx.z;
    const int bm0 = blockIdx.x*128;
    const int k0n = blockIdx.y*64;
    const int bT = bm0>>8, c0 = bm0&255;
    const size_t abase = ((size_t)bT*MM + m)*CEMB + c0;
    const ushort_t* __restrict__ Wh = g_iwh + (size_t)m*LL*KLAT;
    const ushort_t* __restrict__ Wl = g_iwl + (size_t)m*LL*KLAT;

    const int tid=threadIdx.x, wid=tid>>5, lane=tid&31;
    const int wm=wid>>1, wn=wid&1;
    const int g=lane>>2, tq=lane&3;
    const int la=tid>>4, cq=(tid&15)*8;
    const int bkr=tid>>4, bnq=(tid&15)*4;
    const int lar=(lane&15), lac=(lane>>4)*8;
    const int sel=lane>>3, rowg=lane&7;
    const int m_add=(sel&1)*8, k_add=(sel>>1)*8;

    const uint32_t sb = smem_u32(lsm);
    uint32_t aERH = sb + (LB_ERH + (k_add+rowg)*136 + wm*32 + m_add)*2;
    uint32_t aERL = sb + (LB_ERL + (k_add+rowg)*136 + wm*32 + m_add)*2;
    uint32_t aEIH = sb + (LB_EIH + (k_add+rowg)*136 + wm*32 + m_add)*2;
    uint32_t aEIL = sb + (LB_EIL + (k_add+rowg)*136 + wm*32 + m_add)*2;
    uint32_t aWH  = sb + (LB_WH + lar*72 + wn*32 + lac)*2;
    uint32_t aWL  = sb + (LB_WL + lar*72 + wn*32 + lac)*2;

    float accR[2][4][4], accI[2][4][4];
    #pragma unroll
    for (int i=0;i<2;i++)
        #pragma unroll
        for (int j=0;j<4;j++)
            #pragma unroll
            for (int q=0;q<4;q++){ accR[i][j][q]=0.f; accI[i][j][q]=0.f; }

    {
        float4 r0 = *(const float4*)(g_Er + (size_t)la*RC + abase + cq);
        float4 r1 = *(const float4*)(g_Er + (size_t)la*RC + abase + cq + 4);
        float4 i0 = *(const float4*)(g_Ei + (size_t)la*RC + abase + cq);
        float4 i1 = *(const float4*)(g_Ei + (size_t)la*RC + abase + cq + 4);
        float rv[8]={r0.x,r0.y,r0.z,r0.w,r1.x,r1.y,r1.z,r1.w};
        float iv[8]={i0.x,i0.y,i0.z,i0.w,i1.x,i1.y,i1.z,i1.w};
        unsigned short rh[8], rl[8], ih[8], il[8];
        #pragma unroll
        for (int j=0;j<8;j++){ bfsplit(rv[j], rh[j], rl[j]); bfsplit(iv[j], ih[j], il[j]); }
        int ao = la*136 + cq;
        *(uint4*)&lsm[LB_ERH+ao] = *(uint4*)rh;
        *(uint4*)&lsm[LB_ERL+ao] = *(uint4*)rl;
        *(uint4*)&lsm[LB_EIH+ao] = *(uint4*)ih;
        *(uint4*)&lsm[LB_EIL+ao] = *(uint4*)il;
        int bo = bkr*72 + bnq;
        *(uint2*)&lsm[LB_WH+bo] = *(const uint2*)&Wh[(size_t)bkr*KLAT + k0n + bnq];
        *(uint2*)&lsm[LB_WL+bo] = *(const uint2*)&Wl[(size_t)bkr*KLAT + k0n + bnq];
    }
    __syncthreads();

    int buf=0;
    for (int s=0;s<8;s++){
        float4 pr0, pr1, pi0, pi1; uint2 pwh, pwl;
        bool more = (s+1<8);
        if (more){
            int l0=(s+1)*16;
            pr0 = *(const float4*)(g_Er + (size_t)(l0+la)*RC + abase + cq);
            pr1 = *(const float4*)(g_Er + (size_t)(l0+la)*RC + abase + cq + 4);
            pi0 = *(const float4*)(g_Ei + (size_t)(l0+la)*RC + abase + cq);
            pi1 = *(const float4*)(g_Ei + (size_t)(l0+la)*RC + abase + cq + 4);
            pwh = *(const uint2*)&Wh[(size_t)(l0+bkr)*KLAT + k0n + bnq];
            pwl = *(const uint2*)&Wl[(size_t)(l0+bkr)*KLAT + k0n + bnq];
        }
        const uint32_t aof = buf*LBA*2;
        const uint32_t bof = buf*LBB*2;
        uint32_t erh[2][4], erl[2][4], eih[2][4], eil[2][4];
        LDSM4T(erh[0][0],erh[0][1],erh[0][2],erh[0][3], aERH+aof);
        LDSM4T(erh[1][0],erh[1][1],erh[1][2],erh[1][3], aERH+aof+16*2);
        LDSM4T(erl[0][0],erl[0][1],erl[0][2],erl[0][3], aERL+aof);
        LDSM4T(erl[1][0],erl[1][1],erl[1][2],erl[1][3], aERL+aof+16*2);
        LDSM4T(eih[0][0],eih[0][1],eih[0][2],eih[0][3], aEIH+aof);
        LDSM4T(eih[1][0],eih[1][1],eih[1][2],eih[1][3], aEIH+aof+16*2);
        LDSM4T(eil[0][0],eil[0][1],eil[0][2],eil[0][3], aEIL+aof);
        LDSM4T(eil[1][0],eil[1][1],eil[1][2],eil[1][3], aEIL+aof+16*2);
        uint32_t wh[4][2], wl[4][2];
        LDSM4T(wh[0][0],wh[0][1],wh[1][0],wh[1][1], aWH+bof);
        LDSM4T(wh[2][0],wh[2][1],wh[3][0],wh[3][1], aWH+bof+16*2);
        LDSM4T(wl[0][0],wl[0][1],wl[1][0],wl[1][1], aWL+bof);
        LDSM4T(wl[2][0],wl[2][1],wl[3][0],wl[3][1], aWL+bof+16*2);
        #pragma unroll
        for (int mt=0;mt<2;mt++)
            #pragma unroll
            for (int nt=0;nt<4;nt++){
                MMA_BF16(accR[mt][nt], erh[mt], wh[nt][0], wh[nt][1]);
                MMA_BF16(accR[mt][nt], erh[mt], wl[nt][0], wl[nt][1]);
                MMA_BF16(accR[mt][nt], erl[mt], wh[nt][0], wh[nt][1]);
                MMA_BF16(accI[mt][nt], eih[mt], wh[nt][0], wh[nt][1]);
                MMA_BF16(accI[mt][nt], eih[mt], wl[nt][0], wl[nt][1]);
                MMA_BF16(accI[mt][nt], eil[mt], wh[nt][0], wh[nt][1]);
            }
        if (more){
            int nb = buf^1;
            float rv[8]={pr0.x,pr0.y,pr0.z,pr0.w,pr1.x,pr1.y,pr1.z,pr1.w};
            float iv[8]={pi0.x,pi0.y,pi0.z,pi0.w,pi1.x,pi1.y,pi1.z,pi1.w};
            unsigned short rh[8], rl[8], ih[8], il[8];
            #pragma unroll
            for (int j=0;j<8;j++){ bfsplit(rv[j], rh[j], rl[j]); bfsplit(iv[j], ih[j], il[j]); }
            int ao = nb*LBA + la*136 + cq;
            *(uint4*)&lsm[LB_ERH+ao] = *(uint4*)rh;
            *(uint4*)&lsm[LB_ERL+ao] = *(uint4*)rl;
            *(uint4*)&lsm[LB_EIH+ao] = *(uint4*)ih;
            *(uint4*)&lsm[LB_EIL+ao] = *(uint4*)il;
            int bo = nb*LBB + bkr*72 + bnq;
            *(uint2*)&lsm[LB_WH+bo] = pwh;
            *(uint2*)&lsm[LB_WL+bo] = pwl;
        }
        __syncthreads();
        buf ^= 1;
    }

    #pragma unroll
    for (int mt=0;mt<2;mt++){
        int row = bm0 + wm*32 + mt*16 + g;
        #pragma unroll
        for (int nt=0;nt<4;nt++){
            int col = k0n + wn*32 + nt*8 + 2*tq;
            size_t o0 = (size_t)m*BCK + (size_t)row*KLAT + col;
            size_t o1 = o0 + (size_t)8*KLAT;
            *(float2*)(g_Yr+o0) = make_float2(accR[mt][nt][0], accR[mt][nt][1]);
            *(float2*)(g_Yi+o0) = make_float2(accI[mt][nt][0], accI[mt][nt][1]);
            *(float2*)(g_Yr+o1) = make_float2(accR[mt][nt][2], accR[mt][nt][3]);
            *(float2*)(g_Yi+o1) = make_float2(accI[mt][nt][2], accI[mt][nt][3]);
        }
    }
}

// ---- fft inverse via warp MMA (proven)
#define FI_AH 0
#define FI_AL (2*LBA)
#define FI_BH (4*LBA)
#define FI_BL (4*LBA + 2*LBB)

__global__ void __launch_bounds__(256) k_fftinv_mma(){
    __shared__ __align__(16) __nv_bfloat16 fsm[4*LBA + 4*LBB];
    const int bm0 = blockIdx.x*128;
    const int n0  = blockIdx.y*64;
    const int tid=threadIdx.x, wid=tid>>5, lane=tid&31;
    const int wm=wid>>1, wn=wid&1;
    const int g=lane>>2, tq=lane&3;
    const int la=tid>>4, rq=(tid&15)*8;
    const int bkr=tid>>4, bnq=(tid&15)*4;
    const int lar=(lane&15), lac=(lane>>4)*8;
    const int sel=lane>>3, rowg=lane&7;
    const int m_add=(sel&1)*8, k_add=(sel>>1)*8;

    const uint32_t sb = smem_u32(fsm);
    uint32_t aAH = sb + (FI_AH + (k_add+rowg)*136 + wm*32 + m_add)*2;
    uint32_t aAL = sb + (FI_AL + (k_add+rowg)*136 + wm*32 + m_add)*2;
    uint32_t aBH = sb + (FI_BH + lar*72 + wn*32 + lac)*2;
    uint32_t aBL = sb + (FI_BL + lar*72 + wn*32 + lac)*2;

    float acc[2][4][4];
    #pragma unroll
    for (int i=0;i<2;i++)
        #pragma unroll
        for (int j=0;j<4;j++)
            #pragma unroll
            for (int q=0;q<4;q++) acc[i][j][q]=0.f;

    {
        const float* arr = (la&1) ? g_Yi : g_Yr;
        float4 a0 = *(const float4*)(arr + (size_t)(la>>1)*BCK + bm0 + rq);
        float4 a1 = *(const float4*)(arr + (size_t)(la>>1)*BCK + bm0 + rq + 4);
        float av[8]={a0.x,a0.y,a0.z,a0.w,a1.x,a1.y,a1.z,a1.w};
        unsigned short hh[8], ll[8];
        #pragma unroll
        for (int j=0;j<8;j++) bfsplit(av[j], hh[j], ll[j]);
        int ao = la*136 + rq;
        *(uint4*)&fsm[FI_AH+ao] = *(uint4*)hh;
        *(uint4*)&fsm[FI_AL+ao] = *(uint4*)ll;
        int bo = bkr*72 + bnq;
        *(uint2*)&fsm[FI_BH+bo] = *(const uint2*)&g_dih[(size_t)bkr*NLON + n0 + bnq];
        *(uint2*)&fsm[FI_BL+bo] = *(const uint2*)&g_dil[(size_t)bkr*NLON + n0 + bnq];
    }
    __syncthreads();

    int buf=0;
    const int NST=17;
    for (int s=0;s<NST;s++){
        float4 pa0, pa1; uint2 pbh, pbl;
        bool more = (s+1<NST);
        if (more){
            int c0=(s+1)*16;
            int cm = c0 + la;
            const float* arr = (cm&1) ? g_Yi : g_Yr;
            pa0 = *(const float4*)(arr + (size_t)(cm>>1)*BCK + bm0 + rq);
            pa1 = *(const float4*)(arr + (size_t)(cm>>1)*BCK + bm0 + rq + 4);
            pbh = *(const uint2*)&g_dih[(size_t)(c0+bkr)*NLON + n0 + bnq];
            pbl = *(const uint2*)&g_dil[(size_t)(c0+bkr)*NLON + n0 + bnq];
        }
        const uint32_t aof = buf*LBA*2;
        const uint32_t bof = buf*LBB*2;
        uint32_t ah[2][4], al[2][4], bh[4][2], bl[4][2];
        LDSM4T(ah[0][0],ah[0][1],ah[0][2],ah[0][3], aAH+aof);
        LDSM4T(ah[1][0],ah[1][1],ah[1][2],ah[1][3], aAH+aof+16*2);
        LDSM4T(al[0][0],al[0][1],al[0][2],al[0][3], aAL+aof);
        LDSM4T(al[1][0],al[1][1],al[1][2],al[1][3], aAL+aof+16*2);
        LDSM4T(bh[0][0],bh[0][1],bh[1][0],bh[1][1], aBH+bof);
        LDSM4T(bh[2][0],bh[2][1],bh[3][0],bh[3][1], aBH+bof+16*2);
        LDSM4T(bl[0][0],bl[0][1],bl[1][0],bl[1][1], aBL+bof);
        LDSM4T(bl[2][0],bl[2][1],bl[3][0],bl[3][1], aBL+bof+16*2);
        #pragma unroll
        for (int mt=0;mt<2;mt++)
            #pragma unroll
            for (int nt=0;nt<4;nt++){
                MMA_BF16(acc[mt][nt], ah[mt], bh[nt][0], bh[nt][1]);
                MMA_BF16(acc[mt][nt], ah[mt], bl[nt][0], bl[nt][1]);
                MMA_BF16(acc[mt][nt], al[mt], bh[nt][0], bh[nt][1]);
            }
        if (more){
            int nb = buf^1;
            float av[8]={pa0.x,pa0.y,pa0.z,pa0.w,pa1.x,pa1.y,pa1.z,pa1.w};
            unsigned short hh[8], ll[8];
            #pragma unroll
            for (int j=0;j<8;j++) bfsplit(av[j], hh[j], ll[j]);
            int ao = nb*LBA + la*136 + rq;
            *(uint4*)&fsm[FI_AH+ao] = *(uint4*)hh;
            *(uint4*)&fsm[FI_AL+ao] = *(uint4*)ll;
            int bo = nb*LBB + bkr*72 + bnq;
            *(uint2*)&fsm[FI_BH+bo] = pbh;
            *(uint2*)&fsm[FI_BL+bo] = pbl;
        }
        __syncthreads();
        buf ^= 1;
    }

    #pragma unroll
    for (int mt=0;mt<2;mt++){
        int row = bm0 + wm*32 + mt*16 + g;
        #pragma unroll
        for (int nt=0;nt<4;nt++){
            int col = n0 + wn*32 + nt*8 + 2*tq;
            size_t o0 = (size_t)row*NLON + col;
            size_t o1 = o0 + (size_t)8*NLON;
            float2 h0 = *(const float2*)(g_h+o0);
            float2 h1 = *(const float2*)(g_h+o1);
            *(float2*)(g_h+o0) = make_float2(gelu_tanh(acc[mt][nt][0])+h0.x,
                                             gelu_tanh(acc[mt][nt][1])+h0.y);
            *(float2*)(g_h+o1) = make_float2(gelu_tanh(acc[mt][nt][2])+h1.x,
                                             gelu_tanh(acc[mt][nt][3])+h1.y);
        }
    }
}

// ---- warp-MMA bf16 MLP (proven)
__global__ void __launch_bounds__(256) k_mlp_mma(
    int mode, int K, const float* __restrict__ A, const float* __restrict__ bias)
{
    __shared__ __align__(16) __nv_bfloat16 Ah[2][128][24], Al[2][128][24];
    __shared__ __align__(16) __nv_bfloat16 Bh[2][16][72],  Bl[2][16][72];
    const int pix0 = blockIdx.x*64;
    const int m0   = blockIdx.y*128;
    const int bz   = blockIdx.z;
    const float* __restrict__ Bg = (mode ? g_t : g_h) + (size_t)bz*K*PIX;
    float* __restrict__ Cg       = (mode ? g_h : g_t) + (size_t)bz*(mode?CEMB:HID)*PIX;

    const int tid=threadIdx.x, wid=tid>>5, lane=tid&31;
    const int wm=wid>>1, wn=wid&1;
    const int g=lane>>2, tq=lane&3;
    const int ar=tid>>1, akq=(tid&1)*8;
    const int bkr=tid>>4, bnq=(tid&15)*4;

    const int lar = (lane&15), lac = (lane>>4)*8;
    uint32_t aAh = smem_u32(&Ah[0][wm*32 + lar][lac]);
    uint32_t aAl = smem_u32(&Al[0][wm*32 + lar][lac]);
    uint32_t aB0h = smem_u32(&Bh[0][lar][wn*32 + lac]);
    uint32_t aB0l = smem_u32(&Bl[0][lar][wn*32 + lac]);
    const uint32_t ABUF = sizeof(__nv_bfloat16)*128*24;
    const uint32_t BBUF = sizeof(__nv_bfloat16)*16*72;

    float acc[2][4][4];
    #pragma unroll
    for (int i=0;i<2;i++)
        #pragma unroll
        for (int j=0;j<4;j++)
            #pragma unroll
            for (int q=0;q<4;q++) acc[i][j][q]=0.f;

    {
        float4 a0 = *(const float4*)(A + (size_t)(m0+ar)*K + akq);
        float4 a1 = *(const float4*)(A + (size_t)(m0+ar)*K + akq + 4);
        float4 b0 = *(const float4*)(Bg + (size_t)bkr*PIX + pix0 + bnq);
        float av[8]={a0.x,a0.y,a0.z,a0.w,a1.x,a1.y,a1.z,a1.w};
        unsigned short hh[8], ll[8];
        #pragma unroll
        for (int j=0;j<8;j++) bfsplit(av[j], hh[j], ll[j]);
        *(uint4*)&Ah[0][ar][akq] = *(uint4*)hh;
        *(uint4*)&Al[0][ar][akq] = *(uint4*)ll;
        float bv[4]={b0.x,b0.y,b0.z,b0.w};
        unsigned short bh4[4], bl4[4];
        #pragma unroll
        for (int j=0;j<4;j++) bfsplit(bv[j], bh4[j], bl4[j]);
        *(uint2*)&Bh[0][bkr][bnq] = *(uint2*)bh4;
        *(uint2*)&Bl[0][bkr][bnq] = *(uint2*)bl4;
    }
    __syncthreads();

    const int nstep = K>>4;
    int buf=0;
    for (int s=0;s<nstep;s++){
        float4 pa0, pa1, pb0;
        bool more = (s+1<nstep);
        if (more){
            int k0=(s+1)*16;
            pa0 = *(const float4*)(A + (size_t)(m0+ar)*K + k0 + akq);
            pa1 = *(const float4*)(A + (size_t)(m0+ar)*K + k0 + akq + 4);
            pb0 = *(const float4*)(Bg + (size_t)(k0+bkr)*PIX + pix0 + bnq);
        }
        uint32_t ah[2][4], al[2][4], bh[4][2], bl[4][2];
        uint32_t aoff = buf*ABUF;
        uint32_t boff = buf*BBUF;
        LDSM4(ah[0][0],ah[0][1],ah[0][2],ah[0][3], aAh + aoff);
        LDSM4(ah[1][0],ah[1][1],ah[1][2],ah[1][3], aAh + aoff + 16*24*2);
        LDSM4(al[0][0],al[0][1],al[0][2],al[0][3], aAl + aoff);
        LDSM4(al[1][0],al[1][1],al[1][2],al[1][3], aAl + aoff + 16*24*2);
        LDSM4T(bh[0][0],bh[0][1],bh[1][0],bh[1][1], aB0h + boff);
        LDSM4T(bh[2][0],bh[2][1],bh[3][0],bh[3][1], aB0h + boff + 16*2);
        LDSM4T(bl[0][0],bl[0][1],bl[1][0],bl[1][1], aB0l + boff);
        LDSM4T(bl[2][0],bl[2][1],bl[3][0],bl[3][1], aB0l + boff + 16*2);
        #pragma unroll
        for (int mt=0;mt<2;mt++)
            #pragma unroll
            for (int nt=0;nt<4;nt++){
                MMA_BF16(acc[mt][nt], ah[mt], bh[nt][0], bh[nt][1]);
                MMA_BF16(acc[mt][nt], ah[mt], bl[nt][0], bl[nt][1]);
                MMA_BF16(acc[mt][nt], al[mt], bh[nt][0], bh[nt][1]);
            }
        if (more){
            int nb = buf^1;
            float av[8]={pa0.x,pa0.y,pa0.z,pa0.w,pa1.x,pa1.y,pa1.z,pa1.w};
            unsigned short hh[8], ll[8];
            #pragma unroll
            for (int j=0;j<8;j++) bfsplit(av[j], hh[j], ll[j]);
            *(uint4*)&Ah[nb][ar][akq] = *(uint4*)hh;
            *(uint4*)&Al[nb][ar][akq] = *(uint4*)ll;
            float bv[4]={pb0.x,pb0.y,pb0.z,pb0.w};
            unsigned short bh4[4], bl4[4];
            #pragma unroll
            for (int j=0;j<4;j++) bfsplit(bv[j], bh4[j], bl4[j]);
            *(uint2*)&Bh[nb][bkr][bnq] = *(uint2*)bh4;
            *(uint2*)&Bl[nb][bkr][bnq] = *(uint2*)bl4;
        }
        __syncthreads();
        buf ^= 1;
    }

    #pragma unroll
    for (int mt=0;mt<2;mt++){
        int row = m0 + wm*32 + mt*16 + g;
        float bv0 = bias[row], bv1 = bias[row+8];
        #pragma unroll
        for (int nt=0;nt<4;nt++){
            size_t o0 = (size_t)row*PIX + pix0 + wn*32 + nt*8 + 2*tq;
            size_t o1 = o0 + (size_t)8*PIX;
            if (mode==0){
                float2 v0 = make_float2(gelu_tanh(acc[mt][nt][0]+bv0), gelu_tanh(acc[mt][nt][1]+bv0));
                float2 v1 = make_float2(gelu_tanh(acc[mt][nt][2]+bv1), gelu_tanh(acc[mt][nt][3]+bv1));
                *(float2*)(Cg+o0) = v0;
                *(float2*)(Cg+o1) = v1;
            } else {
                float2 h0 = *(const float2*)(Cg+o0);
                float2 h1 = *(const float2*)(Cg+o1);
                *(float2*)(Cg+o0) = make_float2(acc[mt][nt][0]+bv0+h0.x, acc[mt][nt][1]+bv0+h0.y);
                *(float2*)(Cg+o1) = make_float2(acc[mt][nt][2]+bv1+h1.x, acc[mt][nt][3]+bv1+h1.y);
            }
        }
    }
}

// ---------------- decoder ----------------
__global__ void k_decoder(const float* __restrict__ wdec, const float* __restrict__ bdec,
                          float* __restrict__ out){
    int b  = blockIdx.y;
    int p0 = blockIdx.x*256;
    int t  = threadIdx.x;
    __shared__ float ws[8][256];
    #pragma unroll
    for (int j=0;j<8;j++) ws[j][t] = wdec[j*CEMB + t];
    __syncthreads();
    float acc[8];
    #pragma unroll
    for (int o=0;o<8;o++) acc[o] = bdec[o];
    for (int c=0;c<CEMB;c++){
        float v = g_h[((size_t)b*CEMB + c)*PIX + p0 + t];
        #pragma unroll
        for (int o=0;o<8;o++) acc[o] = fmaf(v, ws[o][c], acc[o]);
    }
    #pragma unroll
    for (int o=0;o<8;o++)
        out[((size_t)b*8 + o)*PIX + p0 + t] = acc[o];
}

// ---------------- launch ----------------
extern "C" void kernel_launch(void* const* d_in, const int* in_sizes, int n_in,
                              void* d_out, int out_size){
    const float* x      = (const float*)d_in[0];
    const float* w_enc  = (const float*)d_in[1];
    const float* b_enc  = (const float*)d_in[2];
    const float* pos    = (const float*)d_in[3];
    const float* spec_w = (const float*)d_in[4];
    const float* w1     = (const float*)d_in[5];
    const float* b1     = (const float*)d_in[6];
    const float* w2     = (const float*)d_in[7];
    const float* b2     = (const float*)d_in[8];
    const float* w_dec  = (const float*)d_in[9];
    const float* b_dec  = (const float*)d_in[10];
    const float* sht_wt = (const float*)d_in[11];
    const float* isht_wt= (const float*)d_in[12];
    float* out = (float*)d_out;

    cudaFuncSetAttribute(k_dhconv_mma, cudaFuncAttributeMaxDynamicSharedMemorySize, DSM_TOTAL);
    cudaFuncSetAttribute(k_legfwd_mma, cudaFuncAttributeMaxDynamicSharedMemorySize, LF_TOTAL);

    ushort_t *wth, *wtl, *iwh, *iwl;
    cudaGetSymbolAddress((void**)&wth, g_wth); cudaGetSymbolAddress((void**)&wtl, g_wtl);
    cudaGetSymbolAddress((void**)&iwh, g_iwh); cudaGetSymbolAddress((void**)&iwl, g_iwl);

    k_dftinit<<<NP,256>>>();
    k_wsplit<<<MM*LL, 128>>>(sht_wt, wth, wtl);
    k_wsplit<<<MM*LL, 128>>>(isht_wt, iwh, iwl);
    k_wtrans<<<dim3(32, CEMB, NLAYER), dim3(32,8)>>>(spec_w);
    k_encoder<<<dim3(PIX/256, BB, 4), 256>>>(x, w_enc, b_enc, pos);

    for (int layer=0; layer<NLAYER; layer++){
        k_fftfwd_mma<<<dim3(BCK/128, 4), 256>>>();
        k_fft_m128<<<BCK/8, 256>>>();
        k_legfwd_mma<<<dim3(BC/128, LL/64, MM), 256, LF_TOTAL>>>();
        k_dhconv_mma<<<dim3(3, 4, LL), 256, DSM_TOTAL>>>(layer);
        k_legbwd_mma<<<dim3(BC/128, KLAT/64, MM), 256>>>();
        k_fftinv_mma<<<dim3(BCK/128, NLON/64), 256>>>();
        k_mlp_mma<<<dim3(PIX/64, HID/128, BB), 256>>>(0, CEMB, w1 + (size_t)layer*HID*CEMB, b1 + layer*HID);
        k_mlp_mma<<<dim3(PIX/64, CEMB/128, BB), 256>>>(1, HID,  w2 + (size_t)layer*CEMB*HID, b2 + layer*CEMB);
    }

    k_decoder<<<dim3(PIX/256, BB), 256>>>(w_dec, b_dec, out);
}

// round 17
// speedup vs baseline: 1.0791x; 1.0068x over previous
#include <cuda_runtime.h>
#include <cuda_bf16.h>
#include <math.h>
#include <stdint.h>

#define BB     2
#define CEMB   256
#define KLAT   128
#define NLON   256
#define MM     129
#define MMP    136
#define LL     128
#define HID    512
#define NLAYER 4
#define PIX    (KLAT*NLON)
#define BC     (BB*CEMB)
#define ROWS2  (BB*MM)
#define RC     (ROWS2*CEMB)
#define BCK    (BC*KLAT)
#define NP     320
#define KINV   272

typedef unsigned long long ull;
typedef unsigned short ushort_t;

// ---------------- scratch ----------------
__device__ float g_h [BB*CEMB*PIX];
__device__ float g_t [BB*HID*PIX];
__device__ float g_Fr[MM*BCK];
__device__ float g_Fi[MM*BCK];
__device__ float g_Dr[LL*RC];
__device__ float g_Di[LL*RC];
__device__ float g_Er[LL*RC];
__device__ float g_Ei[LL*RC];
__device__ float g_Yr[(size_t)MMP*BCK];
__device__ float g_Yi[(size_t)MMP*BCK];
// spec_w bf16 hi/lo planes  [layer][l][i][o]
__device__ ushort_t g_Brh[(size_t)NLAYER*LL*CEMB*CEMB];
__device__ ushort_t g_Brl[(size_t)NLAYER*LL*CEMB*CEMB];
__device__ ushort_t g_Bih[(size_t)NLAYER*LL*CEMB*CEMB];
__device__ ushort_t g_Bil[(size_t)NLAYER*LL*CEMB*CEMB];
// static bf16 hi/lo planes
__device__ ushort_t g_dfh[NLON*NP], g_dfl[NLON*NP];
__device__ ushort_t g_dih[KINV*NLON], g_dil[KINV*NLON];
__device__ ushort_t g_wth[MM*LL*KLAT], g_wtl[MM*LL*KLAT];
__device__ ushort_t g_iwh[MM*LL*KLAT], g_iwl[MM*LL*KLAT];

__device__ __forceinline__ float gelu_tanh(float x){
    float x3 = x*x*x;
    float z = 0.7978845608028654f*fmaf(0.044715f, x3, x);
    float t;
    asm("tanh.approx.f32 %0, %1;" : "=f"(t) : "f"(z));
    return 0.5f*x*(1.f + t);
}
__device__ __forceinline__ void bfsplit(float v, unsigned short &h, unsigned short &l){
    __nv_bfloat16 hb = __float2bfloat16(v);
    float r = v - __bfloat162float(hb);
    h = __bfloat16_as_ushort(hb);
    l = __bfloat16_as_ushort(__float2bfloat16(r));
}
__device__ __forceinline__ float bf2f(unsigned short u){
    return __bfloat162float(__ushort_as_bfloat16(u));
}
__device__ __forceinline__ uint32_t smem_u32(const void* p){
    uint32_t a;
    asm("{ .reg .u64 t; cvta.to.shared.u64 t, %1; cvt.u32.u64 %0, t; }" : "=r"(a) : "l"(p));
    return a;
}
#define LDSM4(r0,r1,r2,r3,addr) \
    asm volatile("ldmatrix.sync.aligned.m8n8.x4.shared.b16 {%0,%1,%2,%3}, [%4];" \
        : "=r"(r0),"=r"(r1),"=r"(r2),"=r"(r3) : "r"(addr))
#define LDSM4T(r0,r1,r2,r3,addr) \
    asm volatile("ldmatrix.sync.aligned.m8n8.x4.trans.shared.b16 {%0,%1,%2,%3}, [%4];" \
        : "=r"(r0),"=r"(r1),"=r"(r2),"=r"(r3) : "r"(addr))
#define MMA_BF16(d, a, b0, b1) \
    asm volatile("mma.sync.aligned.m16n8k16.row.col.f32.bf16.bf16.f32 " \
        "{%0,%1,%2,%3}, {%4,%5,%6,%7}, {%8,%9}, {%0,%1,%2,%3};" \
        : "+f"(d[0]),"+f"(d[1]),"+f"(d[2]),"+f"(d[3]) \
        : "r"(a[0]),"r"(a[1]),"r"(a[2]),"r"(a[3]), "r"(b0),"r"(b1))

// ---------------- init ----------------
__global__ void k_dftinit(){
    int c = blockIdx.x;
    int n = threadIdx.x;
    float fwdv = 0.f, invv = 0.f;
    if (c < 2*MM){
        int m = c >> 1;
        int ph = (m*n) & 255;
        double a = 6.283185307179586476925286766559 * (double)ph / 256.0;
        double base = (c & 1) ? -sin(a) : cos(a);
        fwdv = (float)(base * (6.283185307179586476925286766559/256.0));
        double s = (m==0 || m==MM-1) ? 1.0 : 2.0;
        invv = (float)(base * s);
    }
    unsigned short fh, fl;
    bfsplit(fwdv, fh, fl);
    g_dfh[(size_t)n*NP + c] = fh;
    g_dfl[(size_t)n*NP + c] = fl;
    if (c < KINV){
        unsigned short ih, il;
        bfsplit(invv, ih, il);
        g_dih[(size_t)c*NLON + n] = ih;
        g_dil[(size_t)c*NLON + n] = il;
    }
}

__global__ void k_wsplit(const float* __restrict__ wt, ushort_t* __restrict__ h,
                         ushort_t* __restrict__ l){
    size_t i = (size_t)blockIdx.x*128 + threadIdx.x;
    float v = wt[i];
    unsigned short hh, ll;
    bfsplit(v, hh, ll);
    h[i] = hh;
    l[i] = ll;
}

// spec_w [L][i][o][l][2] -> bf16 planes [layer][l][i][o]; packed uint32 stores
__global__ void k_wtrans(const float* __restrict__ sw){
    __shared__ float2 tile[32][33];
    const int lt = blockIdx.x & 3;
    const int ot = blockIdx.x >> 2;
    const int i  = blockIdx.y;
    const int ly = blockIdx.z;
    const int l0 = lt*32, o0 = ot*32;
    const int x = threadIdx.x, y = threadIdx.y;
    for (int r=y; r<32; r+=8){
        size_t src = (((size_t)(ly*CEMB + i))*CEMB + (o0+r))*LL + l0 + x;
        tile[r][x] = *(const float2*)(sw + src*2);
    }
    __syncthreads();
    const int xx = x & 15, xh = x >> 4;
    #pragma unroll
    for (int j=0;j<2;j++){
        int r = y*2 + xh + 16*j;
        float2 wa = tile[2*xx][r];
        float2 wb = tile[2*xx+1][r];
        unsigned short rha,rla,iha,ila, rhb,rlb,ihb,ilb;
        bfsplit(wa.x, rha, rla); bfsplit(wa.y, iha, ila);
        bfsplit(wb.x, rhb, rlb); bfsplit(wb.y, ihb, ilb);
        size_t dst = (((size_t)(ly*LL + l0 + r))*CEMB + i)*CEMB + o0 + 2*xx;
        *(uint32_t*)&g_Brh[dst] = (uint32_t)rha | ((uint32_t)rhb<<16);
        *(uint32_t*)&g_Brl[dst] = (uint32_t)rla | ((uint32_t)rlb<<16);
        *(uint32_t*)&g_Bih[dst] = (uint32_t)iha | ((uint32_t)ihb<<16);
        *(uint32_t*)&g_Bil[dst] = (uint32_t)ila | ((uint32_t)ilb<<16);
    }
}

// encoder: o-dim split over blockIdx.z
__global__ void k_encoder(const float* __restrict__ x, const float* __restrict__ wenc,
                          const float* __restrict__ benc, const float* __restrict__ pos){
    int b  = blockIdx.y;
    int p0 = blockIdx.x*256;
    int oc = blockIdx.z*64;
    int t  = threadIdx.x;
    __shared__ float ws[64][8];
    if (t < 64){
        #pragma unroll
        for (int j=0;j<8;j++) ws[t][j] = wenc[(oc+t)*8+j];
    }
    __syncthreads();
    float xv[8];
    #pragma unroll
    for (int c=0;c<8;c++) xv[c] = x[((size_t)b*8 + c)*PIX + p0 + t];
    for (int oo=0;oo<64;oo++){
        int o = oc + oo;
        float acc = benc[o];
        #pragma unroll
        for (int c=0;c<8;c++) acc = fmaf(xv[c], ws[oo][c], acc);
        g_h[((size_t)b*CEMB + o)*PIX + p0 + t] = acc + pos[(size_t)o*PIX + p0 + t];
    }
}

// ---- fft forward via warp MMA; blockIdx.y==4 slice computes m=128 bin (fused)
__global__ void __launch_bounds__(256) k_fftfwd_mma(){
    const int bm0 = blockIdx.x*128;
    const int tid=threadIdx.x;

    if (blockIdx.y == 4){
        // fused m=128 bin: rows bm0..bm0+127, one warp per 16 rows
        const int w = tid>>5, lane = tid&31;
        for (int r=0;r<16;r++){
            int row = bm0 + w*16 + r;
            const float4* p = (const float4*)(g_h + (size_t)row*NLON);
            float4 x0 = p[lane], x1 = p[lane+32];
            float s = x0.x-x0.y+x0.z-x0.w + x1.x-x1.y+x1.z-x1.w;
            #pragma unroll
            for (int o=16;o;o>>=1) s += __shfl_xor_sync(0xFFFFFFFFu, s, o);
            if (lane==0) g_Fr[(size_t)128*BCK + row] = s * (6.283185307179586f/256.f);
        }
        return;
    }

    __shared__ __align__(16) __nv_bfloat16 Ah[2][128][24], Al[2][128][24];
    __shared__ __align__(16) __nv_bfloat16 Bh[2][16][72],  Bl[2][16][72];
    const int c0  = blockIdx.y*64;
    const int wid=tid>>5, lane=tid&31;
    const int wm=wid>>1, wn=wid&1;
    const int g=lane>>2, tq=lane&3;
    const int ar=tid>>1, akq=(tid&1)*8;
    const int bkr=tid>>4, bnq=(tid&15)*4;
    const int lar=(lane&15), lac=(lane>>4)*8;
    uint32_t aAh = smem_u32(&Ah[0][wm*32 + lar][lac]);
    uint32_t aAl = smem_u32(&Al[0][wm*32 + lar][lac]);
    uint32_t aBh = smem_u32(&Bh[0][lar][wn*32 + lac]);
    uint32_t aBl = smem_u32(&Bl[0][lar][wn*32 + lac]);
    const uint32_t ABUF = 2*128*24, BBUF = 2*16*72;

    float acc[2][4][4];
    #pragma unroll
    for (int i=0;i<2;i++)
        #pragma unroll
        for (int j=0;j<4;j++)
            #pragma unroll
            for (int q=0;q<4;q++) acc[i][j][q]=0.f;

    {
        float4 a0 = *(const float4*)(g_h + (size_t)(bm0+ar)*NLON + akq);
        float4 a1 = *(const float4*)(g_h + (size_t)(bm0+ar)*NLON + akq + 4);
        float av[8]={a0.x,a0.y,a0.z,a0.w,a1.x,a1.y,a1.z,a1.w};
        unsigned short hh[8], ll[8];
        #pragma unroll
        for (int j=0;j<8;j++) bfsplit(av[j], hh[j], ll[j]);
        *(uint4*)&Ah[0][ar][akq] = *(uint4*)hh;
        *(uint4*)&Al[0][ar][akq] = *(uint4*)ll;
        *(uint2*)&Bh[0][bkr][bnq] = *(const uint2*)&g_dfh[(size_t)bkr*NP + c0 + bnq];
        *(uint2*)&Bl[0][bkr][bnq] = *(const uint2*)&g_dfl[(size_t)bkr*NP + c0 + bnq];
    }
    __syncthreads();

    int buf=0;
    for (int s=0;s<16;s++){
        float4 pa0, pa1; uint2 pbh, pbl;
        bool more = (s+1<16);
        if (more){
            int k0=(s+1)*16;
            pa0 = *(const float4*)(g_h + (size_t)(bm0+ar)*NLON + k0 + akq);
            pa1 = *(const float4*)(g_h + (size_t)(bm0+ar)*NLON + k0 + akq + 4);
            pbh = *(const uint2*)&g_dfh[(size_t)(k0+bkr)*NP + c0 + bnq];
            pbl = *(const uint2*)&g_dfl[(size_t)(k0+bkr)*NP + c0 + bnq];
        }
        uint32_t ah[2][4], al[2][4], bh[4][2], bl[4][2];
        uint32_t aoff = buf*ABUF, boff = buf*BBUF;
        LDSM4(ah[0][0],ah[0][1],ah[0][2],ah[0][3], aAh + aoff);
        LDSM4(ah[1][0],ah[1][1],ah[1][2],ah[1][3], aAh + aoff + 16*24*2);
        LDSM4(al[0][0],al[0][1],al[0][2],al[0][3], aAl + aoff);
        LDSM4(al[1][0],al[1][1],al[1][2],al[1][3], aAl + aoff + 16*24*2);
        LDSM4T(bh[0][0],bh[0][1],bh[1][0],bh[1][1], aBh + boff);
        LDSM4T(bh[2][0],bh[2][1],bh[3][0],bh[3][1], aBh + boff + 16*2);
        LDSM4T(bl[0][0],bl[0][1],bl[1][0],bl[1][1], aBl + boff);
        LDSM4T(bl[2][0],bl[2][1],bl[3][0],bl[3][1], aBl + boff + 16*2);
        #pragma unroll
        for (int mt=0;mt<2;mt++)
            #pragma unroll
            for (int nt=0;nt<4;nt++){
                MMA_BF16(acc[mt][nt], ah[mt], bh[nt][0], bh[nt][1]);
                MMA_BF16(acc[mt][nt], ah[mt], bl[nt][0], bl[nt][1]);
                MMA_BF16(acc[mt][nt], al[mt], bh[nt][0], bh[nt][1]);
            }
        if (more){
            int nb = buf^1;
            float av[8]={pa0.x,pa0.y,pa0.z,pa0.w,pa1.x,pa1.y,pa1.z,pa1.w};
            unsigned short hh[8], ll[8];
            #pragma unroll
            for (int j=0;j<8;j++) bfsplit(av[j], hh[j], ll[j]);
            *(uint4*)&Ah[nb][ar][akq] = *(uint4*)hh;
            *(uint4*)&Al[nb][ar][akq] = *(uint4*)ll;
            *(uint2*)&Bh[nb][bkr][bnq] = pbh;
            *(uint2*)&Bl[nb][bkr][bnq] = pbl;
        }
        __syncthreads();
        buf ^= 1;
    }

    #pragma unroll
    for (int mt=0;mt<2;mt++){
        int row = bm0 + wm*32 + mt*16 + g;
        #pragma unroll
        for (int nt=0;nt<4;nt++){
            int m = (c0 + wn*32 + nt*8 + 2*tq) >> 1;
            size_t o = (size_t)m*BCK + row;
            g_Fr[o]   = acc[mt][nt][0];
            g_Fi[o]   = acc[mt][nt][1];
            g_Fr[o+8] = acc[mt][nt][2];
            g_Fi[o+8] = acc[mt][nt][3];
        }
    }
}

// ---- Legendre fwd via warp MMA (proven)
#define LFA 3072
#define LFB 1536
#define LF_FRH 0
#define LF_FRL (2*LFA)
#define LF_FIH (4*LFA)
#define LF_FIL (6*LFA)
#define LF_WH  (8*LFA)
#define LF_WL  (8*LFA + 2*LFB)
#define LF_TOTAL ((8*LFA + 4*LFB)*2)

__global__ void __launch_bounds__(256) k_legfwd_mma(){
    extern __shared__ __nv_bfloat16 lsm[];
    const int m   = blockIdx.z;
    const int bm0 = blockIdx.x*128;
    const int l0  = blockIdx.y*64;
    const float* __restrict__ Ar = g_Fr + (size_t)m*BCK;
    const float* __restrict__ Ai = g_Fi + (size_t)m*BCK;
    const ushort_t* __restrict__ Wh = g_wth + (size_t)m*LL*KLAT;
    const ushort_t* __restrict__ Wl = g_wtl + (size_t)m*LL*KLAT;

    const int tid=threadIdx.x, wid=tid>>5, lane=tid&31;
    const int wm=wid>>1, wn=wid&1;
    const int g=lane>>2, tq=lane&3;
    const int ar=tid>>1, akq=(tid&1)*8;
    const int br=tid>>2, bkq=(tid&3)*4;
    const int lar=(lane&15), lac=(lane>>4)*8;
    const int sel=lane>>3, rowg=lane&7;
    const int bn_add=(sel>>1)*8, bk_add=(sel&1)*8;

    const uint32_t sb = smem_u32(lsm);
    uint32_t aFRH = sb + (LF_FRH + (wm*32+lar)*24 + lac)*2;
    uint32_t aFRL = sb + (LF_FRL + (wm*32+lar)*24 + lac)*2;
    uint32_t aFIH = sb + (LF_FIH + (wm*32+lar)*24 + lac)*2;
    uint32_t aFIL = sb + (LF_FIL + (wm*32+lar)*24 + lac)*2;
    uint32_t aWH0 = sb + (LF_WH + (wn*32 + bn_add + rowg)*24 + bk_add)*2;
    uint32_t aWL0 = sb + (LF_WL + (wn*32 + bn_add + rowg)*24 + bk_add)*2;

    float accR[2][4][4], accI[2][4][4];
    #pragma unroll
    for (int i=0;i<2;i++)
        #pragma unroll
        for (int j=0;j<4;j++)
            #pragma unroll
            for (int q=0;q<4;q++){ accR[i][j][q]=0.f; accI[i][j][q]=0.f; }

    {
        float4 r0 = *(const float4*)(Ar + (size_t)(bm0+ar)*KLAT + akq);
        float4 r1 = *(const float4*)(Ar + (size_t)(bm0+ar)*KLAT + akq + 4);
        float4 i0 = *(const float4*)(Ai + (size_t)(bm0+ar)*KLAT + akq);
        float4 i1 = *(const float4*)(Ai + (size_t)(bm0+ar)*KLAT + akq + 4);
        float rv[8]={r0.x,r0.y,r0.z,r0.w,r1.x,r1.y,r1.z,r1.w};
        float iv[8]={i0.x,i0.y,i0.z,i0.w,i1.x,i1.y,i1.z,i1.w};
        unsigned short rh[8], rl[8], ih[8], il[8];
        #pragma unroll
        for (int j=0;j<8;j++){ bfsplit(rv[j], rh[j], rl[j]); bfsplit(iv[j], ih[j], il[j]); }
        int ao = ar*24 + akq;
        *(uint4*)&lsm[LF_FRH+ao] = *(uint4*)rh;
        *(uint4*)&lsm[LF_FRL+ao] = *(uint4*)rl;
        *(uint4*)&lsm[LF_FIH+ao] = *(uint4*)ih;
        *(uint4*)&lsm[LF_FIL+ao] = *(uint4*)il;
        int bo = br*24 + bkq;
        *(uint2*)&lsm[LF_WH+bo] = *(const uint2*)&Wh[(size_t)(l0+br)*KLAT + bkq];
        *(uint2*)&lsm[LF_WL+bo] = *(const uint2*)&Wl[(size_t)(l0+br)*KLAT + bkq];
    }
    __syncthreads();

    int buf=0;
    for (int s=0;s<8;s++){
        float4 pr0, pr1, pi0, pi1; uint2 pwh, pwl;
        bool more = (s+1<8);
        if (more){
            int k0=(s+1)*16;
            pr0 = *(const float4*)(Ar + (size_t)(bm0+ar)*KLAT + k0 + akq);
            pr1 = *(const float4*)(Ar + (size_t)(bm0+ar)*KLAT + k0 + akq + 4);
            pi0 = *(const float4*)(Ai + (size_t)(bm0+ar)*KLAT + k0 + akq);
            pi1 = *(const float4*)(Ai + (size_t)(bm0+ar)*KLAT + k0 + akq + 4);
            pwh = *(const uint2*)&Wh[(size_t)(l0+br)*KLAT + k0 + bkq];
            pwl = *(const uint2*)&Wl[(size_t)(l0+br)*KLAT + k0 + bkq];
        }
        const uint32_t aof = buf*LFA*2;
        const uint32_t bof = buf*LFB*2;
        uint32_t frh[2][4], frl[2][4], fih[2][4], fil[2][4];
        LDSM4(frh[0][0],frh[0][1],frh[0][2],frh[0][3], aFRH+aof);
        LDSM4(frh[1][0],frh[1][1],frh[1][2],frh[1][3], aFRH+aof+16*24*2);
        LDSM4(frl[0][0],frl[0][1],frl[0][2],frl[0][3], aFRL+aof);
        LDSM4(frl[1][0],frl[1][1],frl[1][2],frl[1][3], aFRL+aof+16*24*2);
        LDSM4(fih[0][0],fih[0][1],fih[0][2],fih[0][3], aFIH+aof);
        LDSM4(fih[1][0],fih[1][1],fih[1][2],fih[1][3], aFIH+aof+16*24*2);
        LDSM4(fil[0][0],fil[0][1],fil[0][2],fil[0][3], aFIL+aof);
        LDSM4(fil[1][0],fil[1][1],fil[1][2],fil[1][3], aFIL+aof+16*24*2);
        uint32_t wh[4][2], wl[4][2];
        LDSM4(wh[0][0],wh[0][1],wh[1][0],wh[1][1], aWH0+bof);
        LDSM4(wh[2][0],wh[2][1],wh[3][0],wh[3][1], aWH0+bof+16*24*2);
        LDSM4(wl[0][0],wl[0][1],wl[1][0],wl[1][1], aWL0+bof);
        LDSM4(wl[2][0],wl[2][1],wl[3][0],wl[3][1], aWL0+bof+16*24*2);
        #pragma unroll
        for (int mt=0;mt<2;mt++)
            #pragma unroll
            for (int nt=0;nt<4;nt++){
                MMA_BF16(accR[mt][nt], frh[mt], wh[nt][0], wh[nt][1]);
                MMA_BF16(accR[mt][nt], frh[mt], wl[nt][0], wl[nt][1]);
                MMA_BF16(accR[mt][nt], frl[mt], wh[nt][0], wh[nt][1]);
                MMA_BF16(accI[mt][nt], fih[mt], wh[nt][0], wh[nt][1]);
                MMA_BF16(accI[mt][nt], fih[mt], wl[nt][0], wl[nt][1]);
                MMA_BF16(accI[mt][nt], fil[mt], wh[nt][0], wh[nt][1]);
            }
        if (more){
            int nb = buf^1;
            float rv[8]={pr0.x,pr0.y,pr0.z,pr0.w,pr1.x,pr1.y,pr1.z,pr1.w};
            float iv[8]={pi0.x,pi0.y,pi0.z,pi0.w,pi1.x,pi1.y,pi1.z,pi1.w};
            unsigned short rh[8], rl[8], ih[8], il[8];
            #pragma unroll
            for (int j=0;j<8;j++){ bfsplit(rv[j], rh[j], rl[j]); bfsplit(iv[j], ih[j], il[j]); }
            int ao = nb*LFA + ar*24 + akq;
            *(uint4*)&lsm[LF_FRH+ao] = *(uint4*)rh;
            *(uint4*)&lsm[LF_FRL+ao] = *(uint4*)rl;
            *(uint4*)&lsm[LF_FIH+ao] = *(uint4*)ih;
            *(uint4*)&lsm[LF_FIL+ao] = *(uint4*)il;
            int bo = nb*LFB + br*24 + bkq;
            *(uint2*)&lsm[LF_WH+bo] = pwh;
            *(uint2*)&lsm[LF_WL+bo] = pwl;
        }
        __syncthreads();
        buf ^= 1;
    }

    #pragma unroll
    for (int mt=0;mt<2;mt++){
        int row = bm0 + wm*32 + mt*16 + g;
        #pragma unroll
        for (int nt=0;nt<4;nt++){
            int lcol = l0 + wn*32 + nt*8 + 2*tq;
            #pragma unroll
            for (int q=0;q<2;q++){
                int l = lcol + q;
                int r0 = row, r1 = row+8;
                size_t o0 = (((size_t)l*BB + (r0>>8))*MM + m)*CEMB + (r0&255);
                size_t o1 = (((size_t)l*BB + (r1>>8))*MM + m)*CEMB + (r1&255);
                g_Dr[o0] = accR[mt][nt][q];
                g_Di[o0] = accI[mt][nt][q];
                g_Dr[o1] = accR[mt][nt][2+q];
                g_Di[o1] = accI[mt][nt][2+q];
            }
        }
    }
}

// ---- dhconv via warp MMA: bx<2 = MMA rows 0..255; bx==2,by==0 = fused tail rows 256-257
#define DA_BUF 3072
#define DB_BUF 1152
#define DOF_DRH 0
#define DOF_DRL (2*DA_BUF)
#define DOF_DIH (4*DA_BUF)
#define DOF_DIL (6*DA_BUF)
#define DOF_BRH (8*DA_BUF)
#define DOF_BRL (8*DA_BUF + 2*DB_BUF)
#define DOF_BIH (8*DA_BUF + 4*DB_BUF)
#define DOF_BIL (8*DA_BUF + 6*DB_BUF)
#define DOF_BNH (8*DA_BUF + 8*DB_BUF)
#define DOF_BNL (8*DA_BUF + 10*DB_BUF)
#define DSM_TOTAL ((8*DA_BUF + 12*DB_BUF)*2)

__global__ void __launch_bounds__(256) k_dhconv_mma(int layer){
    extern __shared__ __nv_bfloat16 dsm[];
    const int l   = blockIdx.z;
    const size_t wbase = ((size_t)(layer*LL + l))*CEMB*CEMB;
    const int tid = threadIdx.x;

    if (blockIdx.x == 2){
        if (blockIdx.y != 0) return;
        __shared__ float dr[2][CEMB], di[2][CEMB];
        const int o = tid;
        const size_t abase = (size_t)l*RC + (size_t)256*CEMB;
        dr[0][o] = g_Dr[abase + o];
        di[0][o] = g_Di[abase + o];
        dr[1][o] = g_Dr[abase + CEMB + o];
        di[1][o] = g_Di[abase + CEMB + o];
        __syncthreads();
        float er0=0.f, ei0=0.f, er1=0.f, ei1=0.f;
        #pragma unroll 4
        for (int i=0;i<CEMB;i++){
            size_t wb = wbase + (size_t)i*CEMB + o;
            float wr = bf2f(__ldg(&g_Brh[wb])) + bf2f(__ldg(&g_Brl[wb]));
            float wi = bf2f(__ldg(&g_Bih[wb])) + bf2f(__ldg(&g_Bil[wb]));
            float r0=dr[0][i], i0=di[0][i], r1=dr[1][i], i1=di[1][i];
            er0 = fmaf(r0, wr, er0); er0 = fmaf(-i0, wi, er0);
            ei0 = fmaf(r0, wi, ei0); ei0 = fmaf( i0, wr, ei0);
            er1 = fmaf(r1, wr, er1); er1 = fmaf(-i1, wi, er1);
            ei1 = fmaf(r1, wi, ei1); ei1 = fmaf( i1, wr, ei1);
        }
        g_Er[abase + o] = er0;        g_Ei[abase + o] = ei0;
        g_Er[abase + CEMB + o] = er1; g_Ei[abase + CEMB + o] = ei1;
        return;
    }

    const int bm0 = blockIdx.x*128;
    const int o0  = blockIdx.y*64;
    const float* __restrict__ Ar = g_Dr + (size_t)l*RC;
    const float* __restrict__ Ai = g_Di + (size_t)l*RC;

    const int wid=tid>>5, lane=tid&31;
    const int wm=wid>>1, wn=wid&1;
    const int g=lane>>2, tq=lane&3;
    const int ar=tid>>1, akq=(tid&1)*8;
    const int bkr=tid>>4, bnq=(tid&15)*4;
    const int lar=(lane&15), lac=(lane>>4)*8;

    const uint32_t sb = smem_u32(dsm);
    uint32_t aDRH = sb + (DOF_DRH + (wm*32+lar)*24 + lac)*2;
    uint32_t aDRL = sb + (DOF_DRL + (wm*32+lar)*24 + lac)*2;
    uint32_t aDIH = sb + (DOF_DIH + (wm*32+lar)*24 + lac)*2;
    uint32_t aDIL = sb + (DOF_DIL + (wm*32+lar)*24 + lac)*2;
    uint32_t aBRH = sb + (DOF_BRH + lar*72 + wn*32 + lac)*2;
    uint32_t aBRL = sb + (DOF_BRL + lar*72 + wn*32 + lac)*2;
    uint32_t aBIH = sb + (DOF_BIH + lar*72 + wn*32 + lac)*2;
    uint32_t aBIL = sb + (DOF_BIL + lar*72 + wn*32 + lac)*2;
    uint32_t aBNH = sb + (DOF_BNH + lar*72 + wn*32 + lac)*2;
    uint32_t aBNL = sb + (DOF_BNL + lar*72 + wn*32 + lac)*2;

    float accR[2][4][4], accI[2][4][4];
    #pragma unroll
    for (int i=0;i<2;i++)
        #pragma unroll
        for (int j=0;j<4;j++)
            #pragma unroll
            for (int q=0;q<4;q++){ accR[i][j][q]=0.f; accI[i][j][q]=0.f; }

    const int arow = bm0 + ar;

    {
        float4 r0 = *(const float4*)(Ar + (size_t)arow*CEMB + akq);
        float4 r1 = *(const float4*)(Ar + (size_t)arow*CEMB + akq + 4);
        float4 i0 = *(const float4*)(Ai + (size_t)arow*CEMB + akq);
        float4 i1 = *(const float4*)(Ai + (size_t)arow*CEMB + akq + 4);
        float rv[8]={r0.x,r0.y,r0.z,r0.w,r1.x,r1.y,r1.z,r1.w};
        float iv[8]={i0.x,i0.y,i0.z,i0.w,i1.x,i1.y,i1.z,i1.w};
        unsigned short rh[8], rl[8], ih[8], il[8];
        #pragma unroll
        for (int j=0;j<8;j++){ bfsplit(rv[j], rh[j], rl[j]); bfsplit(iv[j], ih[j], il[j]); }
        int ao = ar*24 + akq;
        *(uint4*)&dsm[DOF_DRH+ao] = *(uint4*)rh;
        *(uint4*)&dsm[DOF_DRL+ao] = *(uint4*)rl;
        *(uint4*)&dsm[DOF_DIH+ao] = *(uint4*)ih;
        *(uint4*)&dsm[DOF_DIL+ao] = *(uint4*)il;
        size_t wb = wbase + (size_t)bkr*CEMB + o0 + bnq;
        uint2 wrh2 = *(const uint2*)&g_Brh[wb];
        uint2 wrl2 = *(const uint2*)&g_Brl[wb];
        uint2 wih2 = *(const uint2*)&g_Bih[wb];
        uint2 wil2 = *(const uint2*)&g_Bil[wb];
        uint2 wnh2 = make_uint2(wih2.x^0x80008000u, wih2.y^0x80008000u);
        uint2 wnl2 = make_uint2(wil2.x^0x80008000u, wil2.y^0x80008000u);
        int bo = bkr*72 + bnq;
        *(uint2*)&dsm[DOF_BRH+bo] = wrh2;
        *(uint2*)&dsm[DOF_BRL+bo] = wrl2;
        *(uint2*)&dsm[DOF_BIH+bo] = wih2;
        *(uint2*)&dsm[DOF_BIL+bo] = wil2;
        *(uint2*)&dsm[DOF_BNH+bo] = wnh2;
        *(uint2*)&dsm[DOF_BNL+bo] = wnl2;
    }
    __syncthreads();

    int buf=0;
    for (int s=0;s<16;s++){
        float4 pr0, pr1, pi0, pi1;
        uint2 pwrh, pwrl, pwih, pwil;
        bool more = (s+1<16);
        if (more){
            int k0=(s+1)*16;
            pr0 = *(const float4*)(Ar + (size_t)arow*CEMB + k0 + akq);
            pr1 = *(const float4*)(Ar + (size_t)arow*CEMB + k0 + akq + 4);
            pi0 = *(const float4*)(Ai + (size_t)arow*CEMB + k0 + akq);
            pi1 = *(const float4*)(Ai + (size_t)arow*CEMB + k0 + akq + 4);
            size_t wb = wbase + (size_t)(k0+bkr)*CEMB + o0 + bnq;
            pwrh = *(const uint2*)&g_Brh[wb];
            pwrl = *(const uint2*)&g_Brl[wb];
            pwih = *(const uint2*)&g_Bih[wb];
            pwil = *(const uint2*)&g_Bil[wb];
        }
        const uint32_t aof = buf*DA_BUF*2;
        const uint32_t bof = buf*DB_BUF*2;
        uint32_t drh[2][4], drl[2][4], dih[2][4], dil[2][4];
        LDSM4(drh[0][0],drh[0][1],drh[0][2],drh[0][3], aDRH+aof);
        LDSM4(drh[1][0],drh[1][1],drh[1][2],drh[1][3], aDRH+aof+16*24*2);
        LDSM4(drl[0][0],drl[0][1],drl[0][2],drl[0][3], aDRL+aof);
        LDSM4(drl[1][0],drl[1][1],drl[1][2],drl[1][3], aDRL+aof+16*24*2);
        LDSM4(dih[0][0],dih[0][1],dih[0][2],dih[0][3], aDIH+aof);
        LDSM4(dih[1][0],dih[1][1],dih[1][2],dih[1][3], aDIH+aof+16*24*2);
        LDSM4(dil[0][0],dil[0][1],dil[0][2],dil[0][3], aDIL+aof);
        LDSM4(dil[1][0],dil[1][1],dil[1][2],dil[1][3], aDIL+aof+16*24*2);
        uint32_t brh[4][2], brl[4][2], bih[4][2], bil[4][2], bnh[4][2], bnl[4][2];
        LDSM4T(brh[0][0],brh[0][1],brh[1][0],brh[1][1], aBRH+bof);
        LDSM4T(brh[2][0],brh[2][1],brh[3][0],brh[3][1], aBRH+bof+16*2);
        LDSM4T(brl[0][0],brl[0][1],brl[1][0],brl[1][1], aBRL+bof);
        LDSM4T(brl[2][0],brl[2][1],brl[3][0],brl[3][1], aBRL+bof+16*2);
        LDSM4T(bih[0][0],bih[0][1],bih[1][0],bih[1][1], aBIH+bof);
        LDSM4T(bih[2][0],bih[2][1],bih[3][0],bih[3][1], aBIH+bof+16*2);
        LDSM4T(bil[0][0],bil[0][1],bil[1][0],bil[1][1], aBIL+bof);
        LDSM4T(bil[2][0],bil[2][1],bil[3][0],bil[3][1], aBIL+bof+16*2);
        LDSM4T(bnh[0][0],bnh[0][1],bnh[1][0],bnh[1][1], aBNH+bof);
        LDSM4T(bnh[2][0],bnh[2][1],bnh[3][0],bnh[3][1], aBNH+bof+16*2);
        LDSM4T(bnl[0][0],bnl[0][1],bnl[1][0],bnl[1][1], aBNL+bof);
        LDSM4T(bnl[2][0],bnl[2][1],bnl[3][0],bnl[3][1], aBNL+bof+16*2);
        #pragma unroll
        for (int mt=0;mt<2;mt++)
            #pragma unroll
            for (int nt=0;nt<4;nt++){
                MMA_BF16(accR[mt][nt], drh[mt], brh[nt][0], brh[nt][1]);
                MMA_BF16(accR[mt][nt], drh[mt], brl[nt][0], brl[nt][1]);
                MMA_BF16(accR[mt][nt], drl[mt], brh[nt][0], brh[nt][1]);
                MMA_BF16(accR[mt][nt], dih[mt], bnh[nt][0], bnh[nt][1]);
                MMA_BF16(accR[mt][nt], dih[mt], bnl[nt][0], bnl[nt][1]);
                MMA_BF16(accR[mt][nt], dil[mt], bnh[nt][0], bnh[nt][1]);
                MMA_BF16(accI[mt][nt], drh[mt], bih[nt][0], bih[nt][1]);
                MMA_BF16(accI[mt][nt], drh[mt], bil[nt][0], bil[nt][1]);
                MMA_BF16(accI[mt][nt], drl[mt], bih[nt][0], bih[nt][1]);
                MMA_BF16(accI[mt][nt], dih[mt], brh[nt][0], brh[nt][1]);
                MMA_BF16(accI[mt][nt], dih[mt], brl[nt][0], brl[nt][1]);
                MMA_BF16(accI[mt][nt], dil[mt], brh[nt][0], brh[nt][1]);
            }
        if (more){
            int nb = buf^1;
            float rv[8]={pr0.x,pr0.y,pr0.z,pr0.w,pr1.x,pr1.y,pr1.z,pr1.w};
            float iv[8]={pi0.x,pi0.y,pi0.z,pi0.w,pi1.x,pi1.y,pi1.z,pi1.w};
            unsigned short rh[8], rl[8], ih[8], il[8];
            #pragma unroll
            for (int j=0;j<8;j++){ bfsplit(rv[j], rh[j], rl[j]); bfsplit(iv[j], ih[j], il[j]); }
            int ao = nb*DA_BUF + ar*24 + akq;
            *(uint4*)&dsm[DOF_DRH+ao] = *(uint4*)rh;
            *(uint4*)&dsm[DOF_DRL+ao] = *(uint4*)rl;
            *(uint4*)&dsm[DOF_DIH+ao] = *(uint4*)ih;
            *(uint4*)&dsm[DOF_DIL+ao] = *(uint4*)il;
            uint2 wnh2 = make_uint2(pwih.x^0x80008000u, pwih.y^0x80008000u);
            uint2 wnl2 = make_uint2(pwil.x^0x80008000u, pwil.y^0x80008000u);
            int bo = nb*DB_BUF + bkr*72 + bnq;
            *(uint2*)&dsm[DOF_BRH+bo] = pwrh;
            *(uint2*)&dsm[DOF_BRL+bo] = pwrl;
            *(uint2*)&dsm[DOF_BIH+bo] = pwih;
            *(uint2*)&dsm[DOF_BIL+bo] = pwil;
            *(uint2*)&dsm[DOF_BNH+bo] = wnh2;
            *(uint2*)&dsm[DOF_BNL+bo] = wnl2;
        }
        __syncthreads();
        buf ^= 1;
    }

    #pragma unroll
    for (int mt=0;mt<2;mt++){
        int row = bm0 + wm*32 + mt*16 + g;
        #pragma unroll
        for (int nt=0;nt<4;nt++){
            int col = o0 + wn*32 + nt*8 + 2*tq;
            size_t o = (size_t)l*RC + (size_t)row*CEMB + col;
            *(float2*)(g_Er+o) = make_float2(accR[mt][nt][0], accR[mt][nt][1]);
            *(float2*)(g_Ei+o) = make_float2(accI[mt][nt][0], accI[mt][nt][1]);
            size_t o2 = o + (size_t)8*CEMB;
            *(float2*)(g_Er+o2) = make_float2(accR[mt][nt][2], accR[mt][nt][3]);
            *(float2*)(g_Ei+o2) = make_float2(accI[mt][nt][2], accI[mt][nt][3]);
        }
    }
}

// ---- Legendre bwd via warp MMA (proven)
#define LBA 2176
#define LBB 1152
#define LB_ERH 0
#define LB_ERL (2*LBA)
#define LB_EIH (4*LBA)
#define LB_EIL (6*LBA)
#define LB_WH  (8*LBA)
#define LB_WL  (8*LBA + 2*LBB)

__global__ void __launch_bounds__(256) k_legbwd_mma(){
    __shared__ __align__(16) __nv_bfloat16 lsm[8*LBA + 4*LBB];
    const int m   = blockIdx.z;
    const int bm0 = blockIdx.x*128;
    const int k0n = blockIdx.y*64;
    const int bT = bm0>>8, c0 = bm0&255;
    const size_t abase = ((size_t)bT*MM + m)*CEMB + c0;
    const ushort_t* __restrict__ Wh = g_iwh + (size_t)m*LL*KLAT;
    const ushort_t* __restrict__ Wl = g_iwl + (size_t)m*LL*KLAT;

    const int tid=threadIdx.x, wid=tid>>5, lane=tid&31;
    const int wm=wid>>1, wn=wid&1;
    const int g=lane>>2, tq=lane&3;
    const int la=tid>>4, cq=(tid&15)*8;
    const int bkr=tid>>4, bnq=(tid&15)*4;
    const int lar=(lane&15), lac=(lane>>4)*8;
    const int sel=lane>>3, rowg=lane&7;
    const int m_add=(sel&1)*8, k_add=(sel>>1)*8;

    const uint32_t sb = smem_u32(lsm);
    uint32_t aERH = sb + (LB_ERH + (k_add+rowg)*136 + wm*32 + m_add)*2;
    uint32_t aERL = sb + (LB_ERL + (k_add+rowg)*136 + wm*32 + m_add)*2;
    uint32_t aEIH = sb + (LB_EIH + (k_add+rowg)*136 + wm*32 + m_add)*2;
    uint32_t aEIL = sb + (LB_EIL + (k_add+rowg)*136 + wm*32 + m_add)*2;
    uint32_t aWH  = sb + (LB_WH + lar*72 + wn*32 + lac)*2;
    uint32_t aWL  = sb + (LB_WL + lar*72 + wn*32 + lac)*2;

    float accR[2][4][4], accI[2][4][4];
    #pragma unroll
    for (int i=0;i<2;i++)
        #pragma unroll
        for (int j=0;j<4;j++)
            #pragma unroll
            for (int q=0;q<4;q++){ accR[i][j][q]=0.f; accI[i][j][q]=0.f; }

    {
        float4 r0 = *(const float4*)(g_Er + (size_t)la*RC + abase + cq);
        float4 r1 = *(const float4*)(g_Er + (size_t)la*RC + abase + cq + 4);
        float4 i0 = *(const float4*)(g_Ei + (size_t)la*RC + abase + cq);
        float4 i1 = *(const float4*)(g_Ei + (size_t)la*RC + abase + cq + 4);
        float rv[8]={r0.x,r0.y,r0.z,r0.w,r1.x,r1.y,r1.z,r1.w};
        float iv[8]={i0.x,i0.y,i0.z,i0.w,i1.x,i1.y,i1.z,i1.w};
        unsigned short rh[8], rl[8], ih[8], il[8];
        #pragma unroll
        for (int j=0;j<8;j++){ bfsplit(rv[j], rh[j], rl[j]); bfsplit(iv[j], ih[j], il[j]); }
        int ao = la*136 + cq;
        *(uint4*)&lsm[LB_ERH+ao] = *(uint4*)rh;
        *(uint4*)&lsm[LB_ERL+ao] = *(uint4*)rl;
        *(uint4*)&lsm[LB_EIH+ao] = *(uint4*)ih;
        *(uint4*)&lsm[LB_EIL+ao] = *(uint4*)il;
        int bo = bkr*72 + bnq;
        *(uint2*)&lsm[LB_WH+bo] = *(const uint2*)&Wh[(size_t)bkr*KLAT + k0n + bnq];
        *(uint2*)&lsm[LB_WL+bo] = *(const uint2*)&Wl[(size_t)bkr*KLAT + k0n + bnq];
    }
    __syncthreads();

    int buf=0;
    for (int s=0;s<8;s++){
        float4 pr0, pr1, pi0, pi1; uint2 pwh, pwl;
        bool more = (s+1<8);
        if (more){
            int l0=(s+1)*16;
            pr0 = *(const float4*)(g_Er + (size_t)(l0+la)*RC + abase + cq);
            pr1 = *(const float4*)(g_Er + (size_t)(l0+la)*RC + abase + cq + 4);
            pi0 = *(const float4*)(g_Ei + (size_t)(l0+la)*RC + abase + cq);
            pi1 = *(const float4*)(g_Ei + (size_t)(l0+la)*RC + abase + cq + 4);
            pwh = *(const uint2*)&Wh[(size_t)(l0+bkr)*KLAT + k0n + bnq];
            pwl = *(const uint2*)&Wl[(size_t)(l0+bkr)*KLAT + k0n + bnq];
        }
        const uint32_t aof = buf*LBA*2;
        const uint32_t bof = buf*LBB*2;
        uint32_t erh[2][4], erl[2][4], eih[2][4], eil[2][4];
        LDSM4T(erh[0][0],erh[0][1],erh[0][2],erh[0][3], aERH+aof);
        LDSM4T(erh[1][0],erh[1][1],erh[1][2],erh[1][3], aERH+aof+16*2);
        LDSM4T(erl[0][0],erl[0][1],erl[0][2],erl[0][3], aERL+aof);
        LDSM4T(erl[1][0],erl[1][1],erl[1][2],erl[1][3], aERL+aof+16*2);
        LDSM4T(eih[0][0],eih[0][1],eih[0][2],eih[0][3], aEIH+aof);
        LDSM4T(eih[1][0],eih[1][1],eih[1][2],eih[1][3], aEIH+aof+16*2);
        LDSM4T(eil[0][0],eil[0][1],eil[0][2],eil[0][3], aEIL+aof);
        LDSM4T(eil[1][0],eil[1][1],eil[1][2],eil[1][3], aEIL+aof+16*2);
        uint32_t wh[4][2], wl[4][2];
        LDSM4T(wh[0][0],wh[0][1],wh[1][0],wh[1][1], aWH+bof);
        LDSM4T(wh[2][0],wh[2][1],wh[3][0],wh[3][1], aWH+bof+16*2);
        LDSM4T(wl[0][0],wl[0][1],wl[1][0],wl[1][1], aWL+bof);
        LDSM4T(wl[2][0],wl[2][1],wl[3][0],wl[3][1], aWL+bof+16*2);
        #pragma unroll
        for (int mt=0;mt<2;mt++)
            #pragma unroll
            for (int nt=0;nt<4;nt++){
                MMA_BF16(accR[mt][nt], erh[mt], wh[nt][0], wh[nt][1]);
                MMA_BF16(accR[mt][nt], erh[mt], wl[nt][0], wl[nt][1]);
                MMA_BF16(accR[mt][nt], erl[mt], wh[nt][0], wh[nt][1]);
                MMA_BF16(accI[mt][nt], eih[mt], wh[nt][0], wh[nt][1]);
                MMA_BF16(accI[mt][nt], eih[mt], wl[nt][0], wl[nt][1]);
                MMA_BF16(accI[mt][nt], eil[mt], wh[nt][0], wh[nt][1]);
            }
        if (more){
            int nb = buf^1;
            float rv[8]={pr0.x,pr0.y,pr0.z,pr0.w,pr1.x,pr1.y,pr1.z,pr1.w};
            float iv[8]={pi0.x,pi0.y,pi0.z,pi0.w,pi1.x,pi1.y,pi1.z,pi1.w};
            unsigned short rh[8], rl[8], ih[8], il[8];
            #pragma unroll
            for (int j=0;j<8;j++){ bfsplit(rv[j], rh[j], rl[j]); bfsplit(iv[j], ih[j], il[j]); }
            int ao = nb*LBA + la*136 + cq;
            *(uint4*)&lsm[LB_ERH+ao] = *(uint4*)rh;
            *(uint4*)&lsm[LB_ERL+ao] = *(uint4*)rl;
            *(uint4*)&lsm[LB_EIH+ao] = *(uint4*)ih;
            *(uint4*)&lsm[LB_EIL+ao] = *(uint4*)il;
            int bo = nb*LBB + bkr*72 + bnq;
            *(uint2*)&lsm[LB_WH+bo] = pwh;
            *(uint2*)&lsm[LB_WL+bo] = pwl;
        }
        __syncthreads();
        buf ^= 1;
    }

    #pragma unroll
    for (int mt=0;mt<2;mt++){
        int row = bm0 + wm*32 + mt*16 + g;
        #pragma unroll
        for (int nt=0;nt<4;nt++){
            int col = k0n + wn*32 + nt*8 + 2*tq;
            size_t o0 = (size_t)m*BCK + (size_t)row*KLAT + col;
            size_t o1 = o0 + (size_t)8*KLAT;
            *(float2*)(g_Yr+o0) = make_float2(accR[mt][nt][0], accR[mt][nt][1]);
            *(float2*)(g_Yi+o0) = make_float2(accI[mt][nt][0], accI[mt][nt][1]);
            *(float2*)(g_Yr+o1) = make_float2(accR[mt][nt][2], accR[mt][nt][3]);
            *(float2*)(g_Yi+o1) = make_float2(accI[mt][nt][2], accI[mt][nt][3]);
        }
    }
}

// ---- fft inverse via warp MMA (proven)
#define FI_AH 0
#define FI_AL (2*LBA)
#define FI_BH (4*LBA)
#define FI_BL (4*LBA + 2*LBB)

__global__ void __launch_bounds__(256) k_fftinv_mma(){
    __shared__ __align__(16) __nv_bfloat16 fsm[4*LBA + 4*LBB];
    const int bm0 = blockIdx.x*128;
    const int n0  = blockIdx.y*64;
    const int tid=threadIdx.x, wid=tid>>5, lane=tid&31;
    const int wm=wid>>1, wn=wid&1;
    const int g=lane>>2, tq=lane&3;
    const int la=tid>>4, rq=(tid&15)*8;
    const int bkr=tid>>4, bnq=(tid&15)*4;
    const int lar=(lane&15), lac=(lane>>4)*8;
    const int sel=lane>>3, rowg=lane&7;
    const int m_add=(sel&1)*8, k_add=(sel>>1)*8;

    const uint32_t sb = smem_u32(fsm);
    uint32_t aAH = sb + (FI_AH + (k_add+rowg)*136 + wm*32 + m_add)*2;
    uint32_t aAL = sb + (FI_AL + (k_add+rowg)*136 + wm*32 + m_add)*2;
    uint32_t aBH = sb + (FI_BH + lar*72 + wn*32 + lac)*2;
    uint32_t aBL = sb + (FI_BL + lar*72 + wn*32 + lac)*2;

    float acc[2][4][4];
    #pragma unroll
    for (int i=0;i<2;i++)
        #pragma unroll
        for (int j=0;j<4;j++)
            #pragma unroll
            for (int q=0;q<4;q++) acc[i][j][q]=0.f;

    {
        const float* arr = (la&1) ? g_Yi : g_Yr;
        float4 a0 = *(const float4*)(arr + (size_t)(la>>1)*BCK + bm0 + rq);
        float4 a1 = *(const float4*)(arr + (size_t)(la>>1)*BCK + bm0 + rq + 4);
        float av[8]={a0.x,a0.y,a0.z,a0.w,a1.x,a1.y,a1.z,a1.w};
        unsigned short hh[8], ll[8];
        #pragma unroll
        for (int j=0;j<8;j++) bfsplit(av[j], hh[j], ll[j]);
        int ao = la*136 + rq;
        *(uint4*)&fsm[FI_AH+ao] = *(uint4*)hh;
        *(uint4*)&fsm[FI_AL+ao] = *(uint4*)ll;
        int bo = bkr*72 + bnq;
        *(uint2*)&fsm[FI_BH+bo] = *(const uint2*)&g_dih[(size_t)bkr*NLON + n0 + bnq];
        *(uint2*)&fsm[FI_BL+bo] = *(const uint2*)&g_dil[(size_t)bkr*NLON + n0 + bnq];
    }
    __syncthreads();

    int buf=0;
    const int NST=17;
    for (int s=0;s<NST;s++){
        float4 pa0, pa1; uint2 pbh, pbl;
        bool more = (s+1<NST);
        if (more){
            int c0=(s+1)*16;
            int cm = c0 + la;
            const float* arr = (cm&1) ? g_Yi : g_Yr;
            pa0 = *(const float4*)(arr + (size_t)(cm>>1)*BCK + bm0 + rq);
            pa1 = *(const float4*)(arr + (size_t)(cm>>1)*BCK + bm0 + rq + 4);
            pbh = *(const uint2*)&g_dih[(size_t)(c0+bkr)*NLON + n0 + bnq];
            pbl = *(const uint2*)&g_dil[(size_t)(c0+bkr)*NLON + n0 + bnq];
        }
        const uint32_t aof = buf*LBA*2;
        const uint32_t bof = buf*LBB*2;
        uint32_t ah[2][4], al[2][4], bh[4][2], bl[4][2];
        LDSM4T(ah[0][0],ah[0][1],ah[0][2],ah[0][3], aAH+aof);
        LDSM4T(ah[1][0],ah[1][1],ah[1][2],ah[1][3], aAH+aof+16*2);
        LDSM4T(al[0][0],al[0][1],al[0][2],al[0][3], aAL+aof);
        LDSM4T(al[1][0],al[1][1],al[1][2],al[1][3], aAL+aof+16*2);
        LDSM4T(bh[0][0],bh[0][1],bh[1][0],bh[1][1], aBH+bof);
        LDSM4T(bh[2][0],bh[2][1],bh[3][0],bh[3][1], aBH+bof+16*2);
        LDSM4T(bl[0][0],bl[0][1],bl[1][0],bl[1][1], aBL+bof);
        LDSM4T(bl[2][0],bl[2][1],bl[3][0],bl[3][1], aBL+bof+16*2);
        #pragma unroll
        for (int mt=0;mt<2;mt++)
            #pragma unroll
            for (int nt=0;nt<4;nt++){
                MMA_BF16(acc[mt][nt], ah[mt], bh[nt][0], bh[nt][1]);
                MMA_BF16(acc[mt][nt], ah[mt], bl[nt][0], bl[nt][1]);
                MMA_BF16(acc[mt][nt], al[mt], bh[nt][0], bh[nt][1]);
            }
        if (more){
            int nb = buf^1;
            float av[8]={pa0.x,pa0.y,pa0.z,pa0.w,pa1.x,pa1.y,pa1.z,pa1.w};
            unsigned short hh[8], ll[8];
            #pragma unroll
            for (int j=0;j<8;j++) bfsplit(av[j], hh[j], ll[j]);
            int ao = nb*LBA + la*136 + rq;
            *(uint4*)&fsm[FI_AH+ao] = *(uint4*)hh;
            *(uint4*)&fsm[FI_AL+ao] = *(uint4*)ll;
            int bo = nb*LBB + bkr*72 + bnq;
            *(uint2*)&fsm[FI_BH+bo] = pbh;
            *(uint2*)&fsm[FI_BL+bo] = pbl;
        }
        __syncthreads();
        buf ^= 1;
    }

    #pragma unroll
    for (int mt=0;mt<2;mt++){
        int row = bm0 + wm*32 + mt*16 + g;
        #pragma unroll
        for (int nt=0;nt<4;nt++){
            int col = n0 + wn*32 + nt*8 + 2*tq;
            size_t o0 = (size_t)row*NLON + col;
            size_t o1 = o0 + (size_t)8*NLON;
            float2 h0 = *(const float2*)(g_h+o0);
            float2 h1 = *(const float2*)(g_h+o1);
            *(float2*)(g_h+o0) = make_float2(gelu_tanh(acc[mt][nt][0])+h0.x,
                                             gelu_tanh(acc[mt][nt][1])+h0.y);
            *(float2*)(g_h+o1) = make_float2(gelu_tanh(acc[mt][nt][2])+h1.x,
                                             gelu_tanh(acc[mt][nt][3])+h1.y);
        }
    }
}

// ---- warp-MMA bf16 MLP (proven)
__global__ void __launch_bounds__(256) k_mlp_mma(
    int mode, int K, const float* __restrict__ A, const float* __restrict__ bias)
{
    __shared__ __align__(16) __nv_bfloat16 Ah[2][128][24], Al[2][128][24];
    __shared__ __align__(16) __nv_bfloat16 Bh[2][16][72],  Bl[2][16][72];
    const int pix0 = blockIdx.x*64;
    const int m0   = blockIdx.y*128;
    const int bz   = blockIdx.z;
    const float* __restrict__ Bg = (mode ? g_t : g_h) + (size_t)bz*K*PIX;
    float* __restrict__ Cg       = (mode ? g_h : g_t) + (size_t)bz*(mode?CEMB:HID)*PIX;

    const int tid=threadIdx.x, wid=tid>>5, lane=tid&31;
    const int wm=wid>>1, wn=wid&1;
    const int g=lane>>2, tq=lane&3;
    const int ar=tid>>1, akq=(tid&1)*8;
    const int bkr=tid>>4, bnq=(tid&15)*4;

    const int lar = (lane&15), lac = (lane>>4)*8;
    uint32_t aAh = smem_u32(&Ah[0][wm*32 + lar][lac]);
    uint32_t aAl = smem_u32(&Al[0][wm*32 + lar][lac]);
    uint32_t aB0h = smem_u32(&Bh[0][lar][wn*32 + lac]);
    uint32_t aB0l = smem_u32(&Bl[0][lar][wn*32 + lac]);
    const uint32_t ABUF = sizeof(__nv_bfloat16)*128*24;
    const uint32_t BBUF = sizeof(__nv_bfloat16)*16*72;

    float acc[2][4][4];
    #pragma unroll
    for (int i=0;i<2;i++)
        #pragma unroll
        for (int j=0;j<4;j++)
            #pragma unroll
            for (int q=0;q<4;q++) acc[i][j][q]=0.f;

    {
        float4 a0 = *(const float4*)(A + (size_t)(m0+ar)*K + akq);
        float4 a1 = *(const float4*)(A + (size_t)(m0+ar)*K + akq + 4);
        float4 b0 = *(const float4*)(Bg + (size_t)bkr*PIX + pix0 + bnq);
        float av[8]={a0.x,a0.y,a0.z,a0.w,a1.x,a1.y,a1.z,a1.w};
        unsigned short hh[8], ll[8];
        #pragma unroll
        for (int j=0;j<8;j++) bfsplit(av[j], hh[j], ll[j]);
        *(uint4*)&Ah[0][ar][akq] = *(uint4*)hh;
        *(uint4*)&Al[0][ar][akq] = *(uint4*)ll;
        float bv[4]={b0.x,b0.y,b0.z,b0.w};
        unsigned short bh4[4], bl4[4];
        #pragma unroll
        for (int j=0;j<4;j++) bfsplit(bv[j], bh4[j], bl4[j]);
        *(uint2*)&Bh[0][bkr][bnq] = *(uint2*)bh4;
        *(uint2*)&Bl[0][bkr][bnq] = *(uint2*)bl4;
    }
    __syncthreads();

    const int nstep = K>>4;
    int buf=0;
    for (int s=0;s<nstep;s++){
        float4 pa0, pa1, pb0;
        bool more = (s+1<nstep);
        if (more){
            int k0=(s+1)*16;
            pa0 = *(const float4*)(A + (size_t)(m0+ar)*K + k0 + akq);
            pa1 = *(const float4*)(A + (size_t)(m0+ar)*K + k0 + akq + 4);
            pb0 = *(const float4*)(Bg + (size_t)(k0+bkr)*PIX + pix0 + bnq);
        }
        uint32_t ah[2][4], al[2][4], bh[4][2], bl[4][2];
        uint32_t aoff = buf*ABUF;
        uint32_t boff = buf*BBUF;
        LDSM4(ah[0][0],ah[0][1],ah[0][2],ah[0][3], aAh + aoff);
        LDSM4(ah[1][0],ah[1][1],ah[1][2],ah[1][3], aAh + aoff + 16*24*2);
        LDSM4(al[0][0],al[0][1],al[0][2],al[0][3], aAl + aoff);
        LDSM4(al[1][0],al[1][1],al[1][2],al[1][3], aAl + aoff + 16*24*2);
        LDSM4T(bh[0][0],bh[0][1],bh[1][0],bh[1][1], aB0h + boff);
        LDSM4T(bh[2][0],bh[2][1],bh[3][0],bh[3][1], aB0h + boff + 16*2);
        LDSM4T(bl[0][0],bl[0][1],bl[1][0],bl[1][1], aB0l + boff);
        LDSM4T(bl[2][0],bl[2][1],bl[3][0],bl[3][1], aB0l + boff + 16*2);
        #pragma unroll
        for (int mt=0;mt<2;mt++)
            #pragma unroll
            for (int nt=0;nt<4;nt++){
                MMA_BF16(acc[mt][nt], ah[mt], bh[nt][0], bh[nt][1]);
                MMA_BF16(acc[mt][nt], ah[mt], bl[nt][0], bl[nt][1]);
                MMA_BF16(acc[mt][nt], al[mt], bh[nt][0], bh[nt][1]);
            }
        if (more){
            int nb = buf^1;
            float av[8]={pa0.x,pa0.y,pa0.z,pa0.w,pa1.x,pa1.y,pa1.z,pa1.w};
            unsigned short hh[8], ll[8];
            #pragma unroll
            for (int j=0;j<8;j++) bfsplit(av[j], hh[j], ll[j]);
            *(uint4*)&Ah[nb][ar][akq] = *(uint4*)hh;
            *(uint4*)&Al[nb][ar][akq] = *(uint4*)ll;
            float bv[4]={pb0.x,pb0.y,pb0.z,pb0.w};
            unsigned short bh4[4], bl4[4];
            #pragma unroll
            for (int j=0;j<4;j++) bfsplit(bv[j], bh4[j], bl4[j]);
            *(uint2*)&Bh[nb][bkr][bnq] = *(uint2*)bh4;
            *(uint2*)&Bl[nb][bkr][bnq] = *(uint2*)bl4;
        }
        __syncthreads();
        buf ^= 1;
    }

    #pragma unroll
    for (int mt=0;mt<2;mt++){
        int row = m0 + wm*32 + mt*16 + g;
        float bv0 = bias[row], bv1 = bias[row+8];
        #pragma unroll
        for (int nt=0;nt<4;nt++){
            size_t o0 = (size_t)row*PIX + pix0 + wn*32 + nt*8 + 2*tq;
            size_t o1 = o0 + (size_t)8*PIX;
            if (mode==0){
                float2 v0 = make_float2(gelu_tanh(acc[mt][nt][0]+bv0), gelu_tanh(acc[mt][nt][1]+bv0));
                float2 v1 = make_float2(gelu_tanh(acc[mt][nt][2]+bv1), gelu_tanh(acc[mt][nt][3]+bv1));
                *(float2*)(Cg+o0) = v0;
                *(float2*)(Cg+o1) = v1;
            } else {
                float2 h0 = *(const float2*)(Cg+o0);
                float2 h1 = *(const float2*)(Cg+o1);
                *(float2*)(Cg+o0) = make_float2(acc[mt][nt][0]+bv0+h0.x, acc[mt][nt][1]+bv0+h0.y);
                *(float2*)(Cg+o1) = make_float2(acc[mt][nt][2]+bv1+h1.x, acc[mt][nt][3]+bv1+h1.y);
            }
        }
    }
}

// ---------------- decoder ----------------
__global__ void k_decoder(const float* __restrict__ wdec, const float* __restrict__ bdec,
                          float* __restrict__ out){
    int b  = blockIdx.y;
    int p0 = blockIdx.x*256;
    int t  = threadIdx.x;
    __shared__ float ws[8][256];
    #pragma unroll
    for (int j=0;j<8;j++) ws[j][t] = wdec[j*CEMB + t];
    __syncthreads();
    float acc[8];
    #pragma unroll
    for (int o=0;o<8;o++) acc[o] = bdec[o];
    for (int c=0;c<CEMB;c++){
        float v = g_h[((size_t)b*CEMB + c)*PIX + p0 + t];
        #pragma unroll
        for (int o=0;o<8;o++) acc[o] = fmaf(v, ws[o][c], acc[o]);
    }
    #pragma unroll
    for (int o=0;o<8;o++)
        out[((size_t)b*8 + o)*PIX + p0 + t] = acc[o];
}

// ---------------- launch ----------------
extern "C" void kernel_launch(void* const* d_in, const int* in_sizes, int n_in,
                              void* d_out, int out_size){
    const float* x      = (const float*)d_in[0];
    const float* w_enc  = (const float*)d_in[1];
    const float* b_enc  = (const float*)d_in[2];
    const float* pos    = (const float*)d_in[3];
    const float* spec_w = (const float*)d_in[4];
    const float* w1     = (const float*)d_in[5];
    const float* b1     = (const float*)d_in[6];
    const float* w2     = (const float*)d_in[7];
    const float* b2     = (const float*)d_in[8];
    const float* w_dec  = (const float*)d_in[9];
    const float* b_dec  = (const float*)d_in[10];
    const float* sht_wt = (const float*)d_in[11];
    const float* isht_wt= (const float*)d_in[12];
    float* out = (float*)d_out;

    cudaFuncSetAttribute(k_dhconv_mma, cudaFuncAttributeMaxDynamicSharedMemorySize, DSM_TOTAL);
    cudaFuncSetAttribute(k_legfwd_mma, cudaFuncAttributeMaxDynamicSharedMemorySize, LF_TOTAL);

    ushort_t *wth, *wtl, *iwh, *iwl;
    cudaGetSymbolAddress((void**)&wth, g_wth); cudaGetSymbolAddress((void**)&wtl, g_wtl);
    cudaGetSymbolAddress((void**)&iwh, g_iwh); cudaGetSymbolAddress((void**)&iwl, g_iwl);

    k_dftinit<<<NP,256>>>();
    k_wsplit<<<MM*LL, 128>>>(sht_wt, wth, wtl);
    k_wsplit<<<MM*LL, 128>>>(isht_wt, iwh, iwl);
    k_wtrans<<<dim3(32, CEMB, NLAYER), dim3(32,8)>>>(spec_w);
    k_encoder<<<dim3(PIX/256, BB, 4), 256>>>(x, w_enc, b_enc, pos);

    for (int layer=0; layer<NLAYER; layer++){
        k_fftfwd_mma<<<dim3(BCK/128, 5), 256>>>();
        k_legfwd_mma<<<dim3(BC/128, LL/64, MM), 256, LF_TOTAL>>>();
        k_dhconv_mma<<<dim3(3, 4, LL), 256, DSM_TOTAL>>>(layer);
        k_legbwd_mma<<<dim3(BC/128, KLAT/64, MM), 256>>>();
        k_fftinv_mma<<<dim3(BCK/128, NLON/64), 256>>>();
        k_mlp_mma<<<dim3(PIX/64, HID/128, BB), 256>>>(0, CEMB, w1 + (size_t)layer*HID*CEMB, b1 + layer*HID);
        k_mlp_mma<<<dim3(PIX/64, CEMB/128, BB), 256>>>(1, HID,  w2 + (size_t)layer*CEMB*HID, b2 + layer*CEMB);
    }

    k_decoder<<<dim3(PIX/256, BB), 256>>>(w_dec, b_dec, out);
}